// round 2
// baseline (speedup 1.0000x reference)
#include <cuda_runtime.h>

#define T_TOK 2048
#define DIM   768
#define HID   3072
#define NEXP  8

// ---------------- scratch (device globals; no allocations allowed) ----------
__device__ int   g_cnt[NEXP];                   // tokens per expert
__device__ int   g_plist[NEXP * T_TOK];         // pair ids (p = 2*t + k) per expert
__device__ float g_pw[2 * T_TOK];               // gate weight per pair p
__device__ float g_hid[2 * T_TOK * HID];        // moe hidden, row = pair p   (~50 MB)
__device__ float g_hs[T_TOK * HID];             // shared hidden              (~25 MB)
__device__ float g_moe[T_TOK * DIM];            // moe output accumulator
__device__ float g_sh[T_TOK * DIM];             // shared expert output

// ---------------- zero scratch ----------------------------------------------
__global__ void zero_kernel() {
    int i = blockIdx.x * blockDim.x + threadIdx.x;
    if (i < NEXP) g_cnt[i] = 0;
    const int n = T_TOK * DIM;
    for (int j = i; j < n; j += gridDim.x * blockDim.x) g_moe[j] = 0.0f;
}

// ---------------- router: one warp per token --------------------------------
__global__ void router_kernel(const float* __restrict__ x,
                              const float* __restrict__ noise,
                              const float* __restrict__ Wr,
                              const float* __restrict__ br) {
    int warp = (blockIdx.x * blockDim.x + threadIdx.x) >> 5;
    int lane = threadIdx.x & 31;
    if (warp >= T_TOK) return;
    const float* xr = x + warp * DIM;
    float acc[8] = {0.f, 0.f, 0.f, 0.f, 0.f, 0.f, 0.f, 0.f};
    for (int j = lane; j < DIM; j += 32) {
        float xv = xr[j];
        const float4* w4 = reinterpret_cast<const float4*>(Wr + j * NEXP);
        float4 wa = w4[0], wb = w4[1];
        acc[0] += xv * wa.x; acc[1] += xv * wa.y;
        acc[2] += xv * wa.z; acc[3] += xv * wa.w;
        acc[4] += xv * wb.x; acc[5] += xv * wb.y;
        acc[6] += xv * wb.z; acc[7] += xv * wb.w;
    }
#pragma unroll
    for (int off = 16; off; off >>= 1) {
#pragma unroll
        for (int e = 0; e < 8; e++)
            acc[e] += __shfl_xor_sync(0xffffffffu, acc[e], off);
    }
    if (lane == 0) {
        float lg[8];
#pragma unroll
        for (int e = 0; e < 8; e++)
            lg[e] = acc[e] + br[e] + 0.1f * noise[warp * NEXP + e];
        int i0 = 0;
#pragma unroll
        for (int e = 1; e < 8; e++) if (lg[e] > lg[i0]) i0 = e;
        int i1 = (i0 == 0) ? 1 : 0;
#pragma unroll
        for (int e = 0; e < 8; e++) if (e != i0 && lg[e] > lg[i1]) i1 = e;
        // softmax over the two selected logits (lg[i0] is the max)
        float e1 = expf(lg[i1] - lg[i0]);
        float w0 = 1.0f / (1.0f + e1);
        float w1 = e1 * w0;
        g_pw[2 * warp]     = w0;
        g_pw[2 * warp + 1] = w1;
        int p0 = atomicAdd(&g_cnt[i0], 1);
        g_plist[i0 * T_TOK + p0] = 2 * warp;
        int p1 = atomicAdd(&g_cnt[i1], 1);
        g_plist[i1 * T_TOK + p1] = 2 * warp + 1;
    }
}

// ---------------- tiled fp32 GEMM, 128x128x8, 256 thr, 8x8 micro-tile -------
// MODE 0: shared layer1: g_hs[r,:] = leaky(x[r,:] @ Ws1 + bs1)
// MODE 1: moe    layer1: g_hid[p,:] = leaky(x[t,:] @ W1[e] + b1[e])
// MODE 2: shared layer2: g_sh[r,:]  = g_hs[r,:] @ Ws2 + bs2
// MODE 3: moe    layer2: g_moe[t,:] += w_p * (g_hid[p,:] @ W2[e] + b2[e])
template <int MODE>
__global__ __launch_bounds__(256)
void gemm_kernel(const float* __restrict__ A,
                 const float* __restrict__ B,
                 const float* __restrict__ bias,
                 int N, int Kd) {
    const int bn = blockIdx.x;   // N tile
    const int bm = blockIdx.y;   // M tile
    int e = 0, M = T_TOK;
    if (MODE == 1 || MODE == 3) {
        e = blockIdx.z;
        M = g_cnt[e];
        if (bm * 128 >= M) return;
    }

    const float* Bp   = B;
    const float* bp   = bias;
    if (MODE == 1) { Bp = B + (size_t)e * DIM * HID; bp = bias + e * HID; }
    if (MODE == 3) { Bp = B + (size_t)e * HID * DIM; bp = bias + e * DIM; }
    Bp += bn * 128;

    __shared__ float As[8][128];
    __shared__ float Bs[8][128];

    const int tid  = threadIdx.x;
    const int arow = tid >> 1;          // 0..127
    const int acol = (tid & 1) * 4;     // 0 or 4
    const int brow = tid >> 5;          // 0..7
    const int bcol = (tid & 31) * 4;    // 0..124
    const int tx   = tid & 15;
    const int ty   = tid >> 4;

    // resolve this thread's A row
    const float* arp = nullptr;
    bool avalid = true;
    {
        int rg = bm * 128 + arow;
        if (MODE == 0) {
            arp = A + (size_t)rg * DIM;
        } else if (MODE == 2) {
            arp = g_hs + (size_t)rg * HID;
        } else {
            avalid = (rg < M);
            int p = avalid ? g_plist[e * T_TOK + rg] : 0;
            if (MODE == 1) arp = A + (size_t)(p >> 1) * DIM;
            else           arp = g_hid + (size_t)p * HID;
        }
    }

    float accu[8][8];
#pragma unroll
    for (int i = 0; i < 8; i++)
#pragma unroll
        for (int j = 0; j < 8; j++) accu[i][j] = 0.0f;

    for (int k0 = 0; k0 < Kd; k0 += 8) {
        float4 av = avalid ? *reinterpret_cast<const float4*>(arp + k0 + acol)
                           : make_float4(0.f, 0.f, 0.f, 0.f);
        float4 bv = *reinterpret_cast<const float4*>(Bp + (size_t)(k0 + brow) * N + bcol);
        __syncthreads();
        As[acol + 0][arow] = av.x;
        As[acol + 1][arow] = av.y;
        As[acol + 2][arow] = av.z;
        As[acol + 3][arow] = av.w;
        *reinterpret_cast<float4*>(&Bs[brow][bcol]) = bv;
        __syncthreads();
#pragma unroll
        for (int k = 0; k < 8; k++) {
            float4 a0 = *reinterpret_cast<const float4*>(&As[k][ty * 8]);
            float4 a1 = *reinterpret_cast<const float4*>(&As[k][ty * 8 + 4]);
            float4 b0 = *reinterpret_cast<const float4*>(&Bs[k][tx * 8]);
            float4 b1 = *reinterpret_cast<const float4*>(&Bs[k][tx * 8 + 4]);
            float ra[8] = {a0.x, a0.y, a0.z, a0.w, a1.x, a1.y, a1.z, a1.w};
            float rb[8] = {b0.x, b0.y, b0.z, b0.w, b1.x, b1.y, b1.z, b1.w};
#pragma unroll
            for (int i = 0; i < 8; i++)
#pragma unroll
                for (int j = 0; j < 8; j++)
                    accu[i][j] += ra[i] * rb[j];
        }
    }

    // epilogue
    float bvv[8];
#pragma unroll
    for (int j = 0; j < 8; j++) bvv[j] = bp[tx * 8 + j];

#pragma unroll
    for (int i = 0; i < 8; i++) {
        int r = bm * 128 + ty * 8 + i;
        if ((MODE == 1 || MODE == 3) && r >= M) continue;
        if (MODE == 0 || MODE == 1) {
            float* dst;
            if (MODE == 0) {
                dst = g_hs + (size_t)r * HID + bn * 128 + tx * 8;
            } else {
                int p = g_plist[e * T_TOK + r];
                dst = g_hid + (size_t)p * HID + bn * 128 + tx * 8;
            }
#pragma unroll
            for (int j = 0; j < 8; j++) {
                float v = accu[i][j] + bvv[j];
                dst[j] = (v > 0.0f) ? v : 0.01f * v;
            }
        } else if (MODE == 2) {
            float* dst = g_sh + (size_t)r * DIM + bn * 128 + tx * 8;
#pragma unroll
            for (int j = 0; j < 8; j++) dst[j] = accu[i][j] + bvv[j];
        } else {  // MODE 3
            int p = g_plist[e * T_TOK + r];
            int t = p >> 1;
            float w = g_pw[p];
            float* dst = g_moe + (size_t)t * DIM + bn * 128 + tx * 8;
#pragma unroll
            for (int j = 0; j < 8; j++)
                atomicAdd(&dst[j], w * (accu[i][j] + bvv[j]));
        }
    }
}

// ---------------- final mix -------------------------------------------------
__global__ void combine_kernel(const float* __restrict__ alpha,
                               const float* __restrict__ beta,
                               float* __restrict__ out) {
    float a = *alpha, b = *beta;
    float m  = fmaxf(a, b);
    float ea = expf(a - m), eb = expf(b - m);
    float inv = 1.0f / (ea + eb);
    float w0 = ea * inv, w1 = eb * inv;
    const int n = T_TOK * DIM;
    for (int i = blockIdx.x * blockDim.x + threadIdx.x; i < n;
         i += gridDim.x * blockDim.x)
        out[i] = w0 * g_sh[i] + w1 * g_moe[i];
}

// ---------------- launch ----------------------------------------------------
extern "C" void kernel_launch(void* const* d_in, const int* in_sizes, int n_in,
                              void* d_out, int out_size) {
    const float* x     = (const float*)d_in[0];
    const float* noise = (const float*)d_in[1];
    const float* Wr    = (const float*)d_in[2];
    const float* br    = (const float*)d_in[3];
    const float* W1    = (const float*)d_in[4];
    const float* b1    = (const float*)d_in[5];
    const float* W2    = (const float*)d_in[6];
    const float* b2    = (const float*)d_in[7];
    const float* Ws1   = (const float*)d_in[8];
    const float* bs1   = (const float*)d_in[9];
    const float* Ws2   = (const float*)d_in[10];
    const float* bs2   = (const float*)d_in[11];
    const float* alpha = (const float*)d_in[12];
    const float* beta  = (const float*)d_in[13];
    float* out = (float*)d_out;

    zero_kernel<<<512, 256>>>();
    router_kernel<<<T_TOK / 4, 128>>>(x, noise, Wr, br);
    // layer 1: moe (gathered) + shared
    gemm_kernel<1><<<dim3(HID / 128, T_TOK / 128, NEXP), 256>>>(x, W1, b1, HID, DIM);
    gemm_kernel<0><<<dim3(HID / 128, T_TOK / 128), 256>>>(x, Ws1, bs1, HID, DIM);
    // layer 2: moe (scatter) + shared
    gemm_kernel<3><<<dim3(DIM / 128, T_TOK / 128, NEXP), 256>>>(nullptr, W2, b2, DIM, HID);
    gemm_kernel<2><<<dim3(DIM / 128, T_TOK / 128), 256>>>(nullptr, Ws2, bs2, DIM, HID);
    combine_kernel<<<1536, 256>>>(alpha, beta, out);
}

// round 4
// speedup vs baseline: 1.9899x; 1.9899x over previous
#include <cuda_runtime.h>
#include <cuda_bf16.h>
#include <cstdint>

#define T_TOK 2048
#define DIM   768
#define HID   3072
#define NEXP  8
#define K3_1  (3 * DIM)   // 2304
#define K3_2  (3 * HID)   // 9216

// ---------------- scratch (device globals) ----------------------------------
__device__ int   g_cnt[NEXP];
__device__ int   g_plist[NEXP * T_TOK];
__device__ float g_pw[2 * T_TOK];
__device__ float g_moe[T_TOK * DIM];
__device__ float g_sh[T_TOK * DIM];

__device__ __align__(16) __nv_bfloat16 g_x3 [(size_t)T_TOK * K3_1];       // [Xhi|Xlo|Xhi]
__device__ __align__(16) __nv_bfloat16 g_hs3[(size_t)T_TOK * K3_2];       // shared hidden split
__device__ __align__(16) __nv_bfloat16 g_h3 [(size_t)2 * T_TOK * K3_2];   // moe hidden split
__device__ __align__(16) __nv_bfloat16 g_w1t [(size_t)NEXP * HID * K3_1]; // [N,3K]=[Whi|Whi|Wlo]
__device__ __align__(16) __nv_bfloat16 g_ws1t[(size_t)HID * K3_1];
__device__ __align__(16) __nv_bfloat16 g_w2t [(size_t)NEXP * DIM * K3_2];
__device__ __align__(16) __nv_bfloat16 g_ws2t[(size_t)DIM * K3_2];

// ---------------- helpers ----------------------------------------------------
__device__ __forceinline__ uint32_t smem_u32(const void* p) {
    uint32_t a;
    asm("{ .reg .u64 t; cvta.to.shared.u64 t, %1; cvt.u32.u64 %0, t; }"
        : "=r"(a) : "l"(p));
    return a;
}
#define CP16(saddr, gptr) \
    asm volatile("cp.async.cg.shared.global [%0], [%1], 16;" \
                 :: "r"(saddr), "l"(gptr) : "memory")
#define CP_COMMIT() asm volatile("cp.async.commit_group;" ::: "memory")
template <int N>
__device__ __forceinline__ void cp_wait() {
    asm volatile("cp.async.wait_group %0;" :: "n"(N) : "memory");
}
#define LDM_X4(r, addr) \
    asm volatile("ldmatrix.sync.aligned.m8n8.x4.shared.b16 {%0,%1,%2,%3}, [%4];" \
                 : "=r"((r)[0]), "=r"((r)[1]), "=r"((r)[2]), "=r"((r)[3]) \
                 : "r"(addr))
__device__ __forceinline__ void mma16816(float* d, const uint32_t* a,
                                         uint32_t b0, uint32_t b1) {
    asm volatile(
        "mma.sync.aligned.m16n8k16.row.col.f32.bf16.bf16.f32 "
        "{%0,%1,%2,%3}, {%4,%5,%6,%7}, {%8,%9}, {%0,%1,%2,%3};"
        : "+f"(d[0]), "+f"(d[1]), "+f"(d[2]), "+f"(d[3])
        : "r"(a[0]), "r"(a[1]), "r"(a[2]), "r"(a[3]), "r"(b0), "r"(b1));
}

// ---------------- zero scratch ----------------------------------------------
__global__ void zero_kernel() {
    int i = blockIdx.x * blockDim.x + threadIdx.x;
    if (i < NEXP) g_cnt[i] = 0;
    const int n = T_TOK * DIM;
    for (int j = i; j < n; j += gridDim.x * blockDim.x) g_moe[j] = 0.0f;
}

// ---------------- router: one warp per token --------------------------------
__global__ void router_kernel(const float* __restrict__ x,
                              const float* __restrict__ noise,
                              const float* __restrict__ Wr,
                              const float* __restrict__ br) {
    int warp = (blockIdx.x * blockDim.x + threadIdx.x) >> 5;
    int lane = threadIdx.x & 31;
    if (warp >= T_TOK) return;
    const float* xr = x + warp * DIM;
    float acc[8] = {0.f, 0.f, 0.f, 0.f, 0.f, 0.f, 0.f, 0.f};
    for (int j = lane; j < DIM; j += 32) {
        float xv = xr[j];
        const float4* w4 = reinterpret_cast<const float4*>(Wr + j * NEXP);
        float4 wa = w4[0], wb = w4[1];
        acc[0] += xv * wa.x; acc[1] += xv * wa.y;
        acc[2] += xv * wa.z; acc[3] += xv * wa.w;
        acc[4] += xv * wb.x; acc[5] += xv * wb.y;
        acc[6] += xv * wb.z; acc[7] += xv * wb.w;
    }
#pragma unroll
    for (int off = 16; off; off >>= 1)
#pragma unroll
        for (int e = 0; e < 8; e++)
            acc[e] += __shfl_xor_sync(0xffffffffu, acc[e], off);
    if (lane == 0) {
        float lg[8];
#pragma unroll
        for (int e = 0; e < 8; e++)
            lg[e] = acc[e] + br[e] + 0.1f * noise[warp * NEXP + e];
        int i0 = 0;
#pragma unroll
        for (int e = 1; e < 8; e++) if (lg[e] > lg[i0]) i0 = e;
        int i1 = (i0 == 0) ? 1 : 0;
#pragma unroll
        for (int e = 0; e < 8; e++) if (e != i0 && lg[e] > lg[i1]) i1 = e;
        float e1 = expf(lg[i1] - lg[i0]);
        float w0 = 1.0f / (1.0f + e1);
        g_pw[2 * warp]     = w0;
        g_pw[2 * warp + 1] = e1 * w0;
        int p0 = atomicAdd(&g_cnt[i0], 1);
        g_plist[i0 * T_TOK + p0] = 2 * warp;
        int p1 = atomicAdd(&g_cnt[i1], 1);
        g_plist[i1 * T_TOK + p1] = 2 * warp + 1;
    }
}

// ---------------- prep: x -> [hi|lo|hi] bf16 --------------------------------
__global__ void prep_x_kernel(const float* __restrict__ x) {
    int i = blockIdx.x * blockDim.x + threadIdx.x;
    const int n = T_TOK * DIM;
    if (i >= n) return;
    int t = i / DIM, k = i % DIM;
    float v = x[i];
    __nv_bfloat16 hi = __float2bfloat16(v);
    __nv_bfloat16 lo = __float2bfloat16(v - __bfloat162float(hi));
    __nv_bfloat16* row = g_x3 + (size_t)t * K3_1;
    row[k] = hi; row[DIM + k] = lo; row[2 * DIM + k] = hi;
}

// ---------------- prep: weight transpose W[K,N] -> WT3[N,3K]=[hi|hi|lo] -----
__global__ void prep_w_kernel(const float* __restrict__ W, int which, int K, int N) {
    int mat = blockIdx.z;
    W += (size_t)mat * K * N;
    __nv_bfloat16* dst;
    switch (which) {
        case 0: dst = g_ws1t; break;
        case 1: dst = g_ws2t; break;
        case 2: dst = g_w1t + (size_t)mat * HID * K3_1; break;
        default: dst = g_w2t + (size_t)mat * DIM * K3_2; break;
    }
    const int K3 = 3 * K;
    __shared__ float t[32][33];
    int n0 = blockIdx.x * 32, k0 = blockIdx.y * 32;
    int tx = threadIdx.x, ty = threadIdx.y;
#pragma unroll
    for (int i = 0; i < 4; i++)
        t[ty + 8 * i][tx] = W[(size_t)(k0 + ty + 8 * i) * N + n0 + tx];
    __syncthreads();
#pragma unroll
    for (int i = 0; i < 4; i++) {
        int n = n0 + ty + 8 * i;
        int k = k0 + tx;
        float v = t[tx][ty + 8 * i];
        __nv_bfloat16 hi = __float2bfloat16(v);
        __nv_bfloat16 lo = __float2bfloat16(v - __bfloat162float(hi));
        __nv_bfloat16* row = dst + (size_t)n * K3;
        row[k] = hi; row[K + k] = hi; row[2 * K + k] = lo;
    }
}

// ---------------- HMMA GEMM: D[128,128] = A3[128,K3] x B3[128,K3]^T ---------
// block 128x128, 8 warps as 4(M) x 2(N); warp tile 32x64; K-chunk 32.
// smem rows padded to 80B (40 bf16) -> conflict-free ldmatrix.
// MODE 0: shared L1  A=g_x3           B=g_ws1t   -> g_hs3 (leaky, split)
// MODE 1: moe    L1  A=g_x3 (gather)  B=g_w1t[e] -> g_h3  (leaky, split)
// MODE 2: shared L2  A=g_hs3          B=g_ws2t   -> g_sh
// MODE 3: moe    L2  A=g_h3 (gather)  B=g_w2t[e] -> atomic g_moe
template <int MODE>
__global__ __launch_bounds__(256)
void mma_gemm(const float* __restrict__ bias) {
    constexpr int K3 = (MODE <= 1) ? K3_1 : K3_2;
    constexpr int S  = K3 / 32;
    constexpr int BUFB = 10240;   // 128 rows * 80B

    const int bn = blockIdx.x, bm = blockIdx.y;
    int e = 0, M = T_TOK;
    if (MODE == 1 || MODE == 3) {
        e = blockIdx.z;
        M = g_cnt[e];
        if (bm * 128 >= M) return;
    }

    const __nv_bfloat16* A;
    const __nv_bfloat16* B;
    if (MODE == 0) { A = g_x3;  B = g_ws1t; }
    if (MODE == 1) { A = g_x3;  B = g_w1t + (size_t)e * HID * K3_1; }
    if (MODE == 2) { A = g_hs3; B = g_ws2t; }
    if (MODE == 3) { A = g_h3;  B = g_w2t + (size_t)e * DIM * K3_2; }
    const __nv_bfloat16* Bp = B + (size_t)(bn * 128) * K3;
    const float* bp = bias + ((MODE == 1) ? e * HID : (MODE == 3) ? e * DIM : 0)
                    + bn * 128;

    __shared__ __align__(16) char sm_a[2][BUFB];
    __shared__ __align__(16) char sm_b[2][BUFB];
    __shared__ int plist_s[128];

    const int tid = threadIdx.x;
    const int lid = tid & 31, wid = tid >> 5;
    const int wm = wid >> 1, wn = wid & 1;

    if (MODE == 1 || MODE == 3) {
        if (tid < 128) {
            int r = bm * 128 + tid;
            plist_s[tid] = (r < M) ? g_plist[e * T_TOK + r] : -1;
        }
        __syncthreads();
    }

    // -------- per-thread cp.async source/dest (row = tid/2, 32B per thread) --
    const int lrow = tid >> 1;
    const int c4   = (tid & 1) * 2;           // 16B units
    const __nv_bfloat16* arow;
    if (MODE == 0)      arow = g_x3  + (size_t)(bm * 128 + lrow) * K3;
    else if (MODE == 2) arow = g_hs3 + (size_t)(bm * 128 + lrow) * K3;
    else {
        int p  = plist_s[lrow];
        int rr = (p >= 0) ? ((MODE == 1) ? (p >> 1) : p) : 0;  // clamp: garbage rows unused
        arow = ((MODE == 1) ? g_x3 : g_h3) + (size_t)rr * K3;
    }
    const __nv_bfloat16* brow = Bp + (size_t)lrow * K3;
    arow += c4 * 8;
    brow += c4 * 8;
    const uint32_t sa0 = smem_u32(sm_a[0]) + lrow * 80 + c4 * 16;
    const uint32_t sb0 = smem_u32(sm_b[0]) + lrow * 80 + c4 * 16;

    // -------- ldmatrix per-lane base addresses ------------------------------
    const uint32_t aBase = smem_u32(sm_a[0])
        + (wm * 32 + ((lid >> 3) & 1) * 8 + (lid & 7)) * 80
        + (((lid >> 4) & 1) * 8) * 2;
    const uint32_t bBase = smem_u32(sm_b[0])
        + (wn * 64 + ((lid >> 4) & 1) * 8 + (lid & 7)) * 80
        + (((lid >> 3) & 1) * 8) * 2;

    float acc[2][8][4];
#pragma unroll
    for (int i = 0; i < 2; i++)
#pragma unroll
        for (int j = 0; j < 8; j++)
#pragma unroll
            for (int k = 0; k < 4; k++) acc[i][j][k] = 0.0f;

    // -------- prologue load chunk 0 -----------------------------------------
    {
        CP16(sa0,      arow);
        CP16(sa0 + 16, arow + 8);
        CP16(sb0,      brow);
        CP16(sb0 + 16, brow + 8);
        CP_COMMIT();
    }

    for (int s = 0; s < S; ++s) {
        const int buf = s & 1;
        if (s + 1 < S) {
            const uint32_t off = (buf ^ 1) * BUFB;
            const __nv_bfloat16* ga = arow + (s + 1) * 32;
            const __nv_bfloat16* gb = brow + (s + 1) * 32;
            CP16(sa0 + off,      ga);
            CP16(sa0 + off + 16, ga + 8);
            CP16(sb0 + off,      gb);
            CP16(sb0 + off + 16, gb + 8);
            CP_COMMIT();
            cp_wait<1>();
        } else {
            cp_wait<0>();
        }
        __syncthreads();

        const uint32_t ab = buf * BUFB;
#pragma unroll
        for (int kk = 0; kk < 32; kk += 16) {
            uint32_t af[2][4], bf[4][4];
#pragma unroll
            for (int mi = 0; mi < 2; mi++)
                LDM_X4(af[mi], aBase + ab + mi * 16 * 80 + kk * 2);
#pragma unroll
            for (int g = 0; g < 4; g++)
                LDM_X4(bf[g], bBase + ab + g * 16 * 80 + kk * 2);
#pragma unroll
            for (int mi = 0; mi < 2; mi++)
#pragma unroll
                for (int g = 0; g < 4; g++) {
                    mma16816(acc[mi][2 * g],     af[mi], bf[g][0], bf[g][1]);
                    mma16816(acc[mi][2 * g + 1], af[mi], bf[g][2], bf[g][3]);
                }
        }
        __syncthreads();
    }

    // -------- epilogue -------------------------------------------------------
    const int lr = lid >> 2;
    const int lc = (lid & 3) * 2;
#pragma unroll
    for (int mi = 0; mi < 2; mi++) {
#pragma unroll
        for (int h = 0; h < 2; h++) {
            int rl = wm * 32 + mi * 16 + h * 8 + lr;
            int r  = bm * 128 + rl;
            int p = 0, t = 0;
            float gw = 0.f;
            if (MODE == 1 || MODE == 3) {
                p = plist_s[rl];
                if (p < 0) continue;
                t = p >> 1;
                gw = g_pw[p];
            }
            if (MODE == 0 || MODE == 1) {
                __nv_bfloat16* dh = (MODE == 0)
                    ? (g_hs3 + (size_t)r * K3_2)
                    : (g_h3  + (size_t)p * K3_2);
#pragma unroll
                for (int nj = 0; nj < 8; nj++) {
                    int cl = wn * 64 + nj * 8 + lc;
                    int jn = bn * 128 + cl;
                    float v0 = acc[mi][nj][2 * h]     + bp[cl];
                    float v1 = acc[mi][nj][2 * h + 1] + bp[cl + 1];
                    v0 = (v0 > 0.f) ? v0 : 0.01f * v0;
                    v1 = (v1 > 0.f) ? v1 : 0.01f * v1;
                    __nv_bfloat16 h0 = __float2bfloat16(v0);
                    __nv_bfloat16 l0 = __float2bfloat16(v0 - __bfloat162float(h0));
                    __nv_bfloat16 h1 = __float2bfloat16(v1);
                    __nv_bfloat16 l1 = __float2bfloat16(v1 - __bfloat162float(h1));
                    __nv_bfloat162 hv; hv.x = h0; hv.y = h1;
                    __nv_bfloat162 lv; lv.x = l0; lv.y = l1;
                    *reinterpret_cast<__nv_bfloat162*>(dh + jn)           = hv;
                    *reinterpret_cast<__nv_bfloat162*>(dh + HID + jn)     = lv;
                    *reinterpret_cast<__nv_bfloat162*>(dh + 2 * HID + jn) = hv;
                }
            } else if (MODE == 2) {
                float* d = g_sh + (size_t)r * DIM;
#pragma unroll
                for (int nj = 0; nj < 8; nj++) {
                    int cl = wn * 64 + nj * 8 + lc;
                    float2 v;
                    v.x = acc[mi][nj][2 * h]     + bp[cl];
                    v.y = acc[mi][nj][2 * h + 1] + bp[cl + 1];
                    *reinterpret_cast<float2*>(d + bn * 128 + cl) = v;
                }
            } else {
                float* d = g_moe + (size_t)t * DIM;
#pragma unroll
                for (int nj = 0; nj < 8; nj++) {
                    int cl = wn * 64 + nj * 8 + lc;
                    float v0 = acc[mi][nj][2 * h]     + bp[cl];
                    float v1 = acc[mi][nj][2 * h + 1] + bp[cl + 1];
                    atomicAdd(d + bn * 128 + cl,     gw * v0);
                    atomicAdd(d + bn * 128 + cl + 1, gw * v1);
                }
            }
        }
    }
}

// ---------------- final mix -------------------------------------------------
__global__ void combine_kernel(const float* __restrict__ alpha,
                               const float* __restrict__ beta,
                               float* __restrict__ out) {
    float a = *alpha, b = *beta;
    float m  = fmaxf(a, b);
    float ea = expf(a - m), eb = expf(b - m);
    float inv = 1.0f / (ea + eb);
    float w0 = ea * inv, w1 = eb * inv;
    const int n = T_TOK * DIM;
    for (int i = blockIdx.x * blockDim.x + threadIdx.x; i < n;
         i += gridDim.x * blockDim.x)
        out[i] = w0 * g_sh[i] + w1 * g_moe[i];
}

// ---------------- launch ----------------------------------------------------
extern "C" void kernel_launch(void* const* d_in, const int* in_sizes, int n_in,
                              void* d_out, int out_size) {
    const float* x     = (const float*)d_in[0];
    const float* noise = (const float*)d_in[1];
    const float* Wr    = (const float*)d_in[2];
    const float* br    = (const float*)d_in[3];
    const float* W1    = (const float*)d_in[4];
    const float* b1    = (const float*)d_in[5];
    const float* W2    = (const float*)d_in[6];
    const float* b2    = (const float*)d_in[7];
    const float* Ws1   = (const float*)d_in[8];
    const float* bs1   = (const float*)d_in[9];
    const float* Ws2   = (const float*)d_in[10];
    const float* bs2   = (const float*)d_in[11];
    const float* alpha = (const float*)d_in[12];
    const float* beta  = (const float*)d_in[13];
    float* out = (float*)d_out;

    zero_kernel<<<512, 256>>>();
    router_kernel<<<T_TOK / 4, 128>>>(x, noise, Wr, br);
    prep_x_kernel<<<(T_TOK * DIM + 255) / 256, 256>>>(x);
    prep_w_kernel<<<dim3(HID / 32, DIM / 32, 1),    dim3(32, 8)>>>(Ws1, 0, DIM, HID);
    prep_w_kernel<<<dim3(DIM / 32, HID / 32, 1),    dim3(32, 8)>>>(Ws2, 1, HID, DIM);
    prep_w_kernel<<<dim3(HID / 32, DIM / 32, NEXP), dim3(32, 8)>>>(W1, 2, DIM, HID);
    prep_w_kernel<<<dim3(DIM / 32, HID / 32, NEXP), dim3(32, 8)>>>(W2, 3, HID, DIM);
    // layer 1
    mma_gemm<1><<<dim3(HID / 128, T_TOK / 128, NEXP), 256>>>(b1);
    mma_gemm<0><<<dim3(HID / 128, T_TOK / 128, 1),    256>>>(bs1);
    // layer 2
    mma_gemm<3><<<dim3(DIM / 128, T_TOK / 128, NEXP), 256>>>(b2);
    mma_gemm<2><<<dim3(DIM / 128, T_TOK / 128, 1),    256>>>(bs2);
    combine_kernel<<<1536, 256>>>(alpha, beta, out);
}

// round 5
// speedup vs baseline: 2.7291x; 1.3715x over previous
#include <cuda_runtime.h>
#include <cuda_fp16.h>
#include <cstdint>

#define T_TOK 2048
#define DIM   768
#define HID   3072
#define NEXP  8
#define K2_1  (2 * DIM)   // A row len layer1
#define K2_2  (2 * HID)   // A row len layer2

// ---------------- scratch (device globals) ----------------------------------
__device__ int   g_cnt[NEXP];
__device__ int   g_plist[NEXP * T_TOK];
__device__ float g_pw[2 * T_TOK];
__device__ float g_moe[T_TOK * DIM];
__device__ float g_sh[T_TOK * DIM];

__device__ __align__(16) __half g_x2 [(size_t)T_TOK * K2_1];        // [xh|xl]
__device__ __align__(16) __half g_hs2[(size_t)T_TOK * K2_2];        // shared hidden [hh|hl]
__device__ __align__(16) __half g_h2 [(size_t)2 * T_TOK * K2_2];    // moe hidden [hh|hl]
__device__ __align__(16) __half g_w1t [(size_t)NEXP * HID * DIM];   // W1^T fp16 [N,K]
__device__ __align__(16) __half g_ws1t[(size_t)HID * DIM];
__device__ __align__(16) __half g_w2t [(size_t)NEXP * DIM * HID];
__device__ __align__(16) __half g_ws2t[(size_t)DIM * HID];

// ---------------- helpers ----------------------------------------------------
__device__ __forceinline__ uint32_t smem_u32(const void* p) {
    uint32_t a;
    asm("{ .reg .u64 t; cvta.to.shared.u64 t, %1; cvt.u32.u64 %0, t; }"
        : "=r"(a) : "l"(p));
    return a;
}
#define CP16(saddr, gptr) \
    asm volatile("cp.async.cg.shared.global [%0], [%1], 16;" \
                 :: "r"(saddr), "l"(gptr) : "memory")
#define CP_COMMIT() asm volatile("cp.async.commit_group;" ::: "memory")
template <int N>
__device__ __forceinline__ void cp_wait() {
    asm volatile("cp.async.wait_group %0;" :: "n"(N) : "memory");
}
#define LDM_X4(r, addr) \
    asm volatile("ldmatrix.sync.aligned.m8n8.x4.shared.b16 {%0,%1,%2,%3}, [%4];" \
                 : "=r"((r)[0]), "=r"((r)[1]), "=r"((r)[2]), "=r"((r)[3]) \
                 : "r"(addr))
__device__ __forceinline__ void mma16816(float* d, const uint32_t* a,
                                         uint32_t b0, uint32_t b1) {
    asm volatile(
        "mma.sync.aligned.m16n8k16.row.col.f32.f16.f16.f32 "
        "{%0,%1,%2,%3}, {%4,%5,%6,%7}, {%8,%9}, {%0,%1,%2,%3};"
        : "+f"(d[0]), "+f"(d[1]), "+f"(d[2]), "+f"(d[3])
        : "r"(a[0]), "r"(a[1]), "r"(a[2]), "r"(a[3]), "r"(b0), "r"(b1));
}

// ---------------- zero scratch ----------------------------------------------
__global__ void zero_kernel() {
    int i = blockIdx.x * blockDim.x + threadIdx.x;
    if (i < NEXP) g_cnt[i] = 0;
    const int n = T_TOK * DIM;
    for (int j = i; j < n; j += gridDim.x * blockDim.x) g_moe[j] = 0.0f;
}

// ---------------- router: one warp per token --------------------------------
__global__ void router_kernel(const float* __restrict__ x,
                              const float* __restrict__ noise,
                              const float* __restrict__ Wr,
                              const float* __restrict__ br) {
    int warp = (blockIdx.x * blockDim.x + threadIdx.x) >> 5;
    int lane = threadIdx.x & 31;
    if (warp >= T_TOK) return;
    const float* xr = x + warp * DIM;
    float acc[8] = {0.f, 0.f, 0.f, 0.f, 0.f, 0.f, 0.f, 0.f};
    for (int j = lane; j < DIM; j += 32) {
        float xv = xr[j];
        const float4* w4 = reinterpret_cast<const float4*>(Wr + j * NEXP);
        float4 wa = w4[0], wb = w4[1];
        acc[0] += xv * wa.x; acc[1] += xv * wa.y;
        acc[2] += xv * wa.z; acc[3] += xv * wa.w;
        acc[4] += xv * wb.x; acc[5] += xv * wb.y;
        acc[6] += xv * wb.z; acc[7] += xv * wb.w;
    }
#pragma unroll
    for (int off = 16; off; off >>= 1)
#pragma unroll
        for (int e = 0; e < 8; e++)
            acc[e] += __shfl_xor_sync(0xffffffffu, acc[e], off);
    if (lane == 0) {
        float lg[8];
#pragma unroll
        for (int e = 0; e < 8; e++)
            lg[e] = acc[e] + br[e] + 0.1f * noise[warp * NEXP + e];
        int i0 = 0;
#pragma unroll
        for (int e = 1; e < 8; e++) if (lg[e] > lg[i0]) i0 = e;
        int i1 = (i0 == 0) ? 1 : 0;
#pragma unroll
        for (int e = 0; e < 8; e++) if (e != i0 && lg[e] > lg[i1]) i1 = e;
        float e1 = expf(lg[i1] - lg[i0]);
        float w0 = 1.0f / (1.0f + e1);
        g_pw[2 * warp]     = w0;
        g_pw[2 * warp + 1] = e1 * w0;
        int p0 = atomicAdd(&g_cnt[i0], 1);
        g_plist[i0 * T_TOK + p0] = 2 * warp;
        int p1 = atomicAdd(&g_cnt[i1], 1);
        g_plist[i1 * T_TOK + p1] = 2 * warp + 1;
    }
}

// ---------------- prep: x -> [xh|xl] fp16 -----------------------------------
__global__ void prep_x_kernel(const float* __restrict__ x) {
    int i = blockIdx.x * blockDim.x + threadIdx.x;
    const int n = T_TOK * DIM;
    if (i >= n) return;
    int t = i / DIM, k = i % DIM;
    float v = x[i];
    __half hi = __float2half(v);
    __half lo = __float2half(v - __half2float(hi));
    __half* row = g_x2 + (size_t)t * K2_1;
    row[k] = hi; row[DIM + k] = lo;
}

// ---------------- prep: weight transpose W[K,N] -> WT[N,K] fp16 -------------
__global__ void prep_w_kernel(const float* __restrict__ W, int which, int K, int N) {
    int mat = blockIdx.z;
    W += (size_t)mat * K * N;
    __half* dst;
    switch (which) {
        case 0: dst = g_ws1t; break;
        case 1: dst = g_ws2t; break;
        case 2: dst = g_w1t + (size_t)mat * HID * DIM; break;
        default: dst = g_w2t + (size_t)mat * DIM * HID; break;
    }
    __shared__ float t[32][33];
    int n0 = blockIdx.x * 32, k0 = blockIdx.y * 32;
    int tx = threadIdx.x, ty = threadIdx.y;
#pragma unroll
    for (int i = 0; i < 4; i++)
        t[ty + 8 * i][tx] = W[(size_t)(k0 + ty + 8 * i) * N + n0 + tx];
    __syncthreads();
#pragma unroll
    for (int i = 0; i < 4; i++) {
        int n = n0 + ty + 8 * i;
        int k = k0 + tx;
        dst[(size_t)n * K + k] = __float2half(t[tx][ty + 8 * i]);
    }
}

// ---------------- HMMA GEMM (2-term fp16): D = (Ah+Al) x Bh^T ---------------
// block 128x128, 8 warps 4(M)x2(N), warp tile 32x64, K-chunk 32.
// A smem: 128 rows x 144B ([hi 64B | lo 64B] + 16B pad), B: 128 rows x 80B.
// B fragments are shared by hi and lo MMAs (B stored once, no duplication).
// MODE 0: shared L1  A=g_x2           B=g_ws1t   -> g_hs2 (leaky, split)
// MODE 1: moe    L1  A=g_x2 (gather)  B=g_w1t[e] -> g_h2  (leaky, split)
// MODE 2: shared L2  A=g_hs2          B=g_ws2t   -> g_sh
// MODE 3: moe    L2  A=g_h2 (gather)  B=g_w2t[e] -> atomic g_moe
template <int MODE>
__global__ __launch_bounds__(256)
void mma_gemm(const float* __restrict__ bias) {
    constexpr int K  = (MODE <= 1) ? DIM : HID;   // true K
    constexpr int AK = 2 * K;                     // A row length (hi|lo)
    constexpr int S  = K / 32;
    constexpr int BUFA = 128 * 144;               // 18432
    constexpr int BUFB = 128 * 80;                // 10240

    const int bn = blockIdx.x, bm = blockIdx.y;
    int e = 0, M = T_TOK;
    if (MODE == 1 || MODE == 3) {
        e = blockIdx.z;
        M = g_cnt[e];
        if (bm * 128 >= M) return;
    }

    const __half* A;
    const __half* B;
    if (MODE == 0) { A = g_x2;  B = g_ws1t; }
    if (MODE == 1) { A = g_x2;  B = g_w1t + (size_t)e * HID * DIM; }
    if (MODE == 2) { A = g_hs2; B = g_ws2t; }
    if (MODE == 3) { A = g_h2;  B = g_w2t + (size_t)e * DIM * HID; }
    const __half* Bp = B + (size_t)(bn * 128) * K;
    const float* bp = bias + ((MODE == 1) ? e * HID : (MODE == 3) ? e * DIM : 0)
                    + bn * 128;

    extern __shared__ __align__(16) char dsm[];
    char* sm_a = dsm;                 // 2 x BUFA
    char* sm_b = dsm + 2 * BUFA;      // 2 x BUFB
    __shared__ int plist_s[128];

    const int tid = threadIdx.x;
    const int lid = tid & 31, wid = tid >> 5;
    const int wm = wid >> 1, wn = wid & 1;

    if (MODE == 1 || MODE == 3) {
        if (tid < 128) {
            int r = bm * 128 + tid;
            plist_s[tid] = (r < M) ? g_plist[e * T_TOK + r] : -1;
        }
        __syncthreads();
    }

    // ---- per-thread cp.async mapping: 2 threads per row ----
    const int lrow = tid >> 1;
    const int half = tid & 1;                      // 0 = hi, 1 = lo (A)
    const __half* arow;                            // A row base + half*K
    if (MODE == 0)      arow = g_x2  + (size_t)(bm * 128 + lrow) * AK;
    else if (MODE == 2) arow = g_hs2 + (size_t)(bm * 128 + lrow) * AK;
    else {
        int p  = plist_s[lrow];
        int rr = (p >= 0) ? ((MODE == 1) ? (p >> 1) : p) : 0;
        arow = ((MODE == 1) ? g_x2 : g_h2) + (size_t)rr * AK;
    }
    arow += half * K;
    const __half* brow = Bp + (size_t)lrow * K + half * 16;
    const uint32_t sa0 = smem_u32(sm_a) + lrow * 144 + half * 64;
    const uint32_t sb0 = smem_u32(sm_b) + lrow * 80 + half * 32;

    // ---- ldmatrix base addresses ----
    const uint32_t aBase = smem_u32(sm_a)
        + (wm * 32 + (lid & 15)) * 144 + ((lid >> 4) & 1) * 16;
    const uint32_t bBase = smem_u32(sm_b)
        + (wn * 64 + ((lid >> 4) & 1) * 8 + (lid & 7)) * 80
        + ((lid >> 3) & 1) * 16;

    float acc[2][8][4];
#pragma unroll
    for (int i = 0; i < 2; i++)
#pragma unroll
        for (int j = 0; j < 8; j++)
#pragma unroll
            for (int k = 0; k < 4; k++) acc[i][j][k] = 0.0f;

    // ---- prologue: stage 0 ----
    {
        CP16(sa0,      arow);
        CP16(sa0 + 16, arow + 8);
        CP16(sa0 + 32, arow + 16);
        CP16(sa0 + 48, arow + 24);
        CP16(sb0,      brow);
        CP16(sb0 + 16, brow + 8);
        CP_COMMIT();
    }

    for (int s = 0; s < S; ++s) {
        const int buf = s & 1;
        if (s + 1 < S) {
            const __half* ga = arow + (s + 1) * 32;
            const __half* gb = brow + (s + 1) * 32;
            const uint32_t da = sa0 + (buf ^ 1) * BUFA;
            const uint32_t db = sb0 + (buf ^ 1) * BUFB;
            CP16(da,      ga);
            CP16(da + 16, ga + 8);
            CP16(da + 32, ga + 16);
            CP16(da + 48, ga + 24);
            CP16(db,      gb);
            CP16(db + 16, gb + 8);
            CP_COMMIT();
            cp_wait<1>();
        } else {
            cp_wait<0>();
        }
        __syncthreads();

        const uint32_t ab = buf * BUFA;
        const uint32_t bb = buf * BUFB;
#pragma unroll
        for (int kk = 0; kk < 32; kk += 16) {
            uint32_t ah[2][4], al[2][4], bf[4][4];
#pragma unroll
            for (int mi = 0; mi < 2; mi++) {
                LDM_X4(ah[mi], aBase + ab + mi * 16 * 144 + kk * 2);
                LDM_X4(al[mi], aBase + ab + mi * 16 * 144 + kk * 2 + 64);
            }
#pragma unroll
            for (int g = 0; g < 4; g++)
                LDM_X4(bf[g], bBase + bb + g * 16 * 80 + kk * 2);
#pragma unroll
            for (int mi = 0; mi < 2; mi++)
#pragma unroll
                for (int g = 0; g < 4; g++) {
                    mma16816(acc[mi][2 * g],     ah[mi], bf[g][0], bf[g][1]);
                    mma16816(acc[mi][2 * g + 1], ah[mi], bf[g][2], bf[g][3]);
                    mma16816(acc[mi][2 * g],     al[mi], bf[g][0], bf[g][1]);
                    mma16816(acc[mi][2 * g + 1], al[mi], bf[g][2], bf[g][3]);
                }
        }
        __syncthreads();
    }

    // ---- epilogue ----
    const int lr = lid >> 2;
    const int lc = (lid & 3) * 2;
#pragma unroll
    for (int mi = 0; mi < 2; mi++) {
#pragma unroll
        for (int h = 0; h < 2; h++) {
            int rl = wm * 32 + mi * 16 + h * 8 + lr;
            int r  = bm * 128 + rl;
            int p = 0, t = 0;
            float gw = 0.f;
            if (MODE == 1 || MODE == 3) {
                p = plist_s[rl];
                if (p < 0) continue;
                t = p >> 1;
                gw = g_pw[p];
            }
            if (MODE == 0 || MODE == 1) {
                __half* dh = (MODE == 0)
                    ? (g_hs2 + (size_t)r * K2_2)
                    : (g_h2  + (size_t)p * K2_2);
#pragma unroll
                for (int nj = 0; nj < 8; nj++) {
                    int cl = wn * 64 + nj * 8 + lc;
                    int jn = bn * 128 + cl;
                    float v0 = acc[mi][nj][2 * h]     + bp[cl];
                    float v1 = acc[mi][nj][2 * h + 1] + bp[cl + 1];
                    v0 = (v0 > 0.f) ? v0 : 0.01f * v0;
                    v1 = (v1 > 0.f) ? v1 : 0.01f * v1;
                    __half h0 = __float2half(v0);
                    __half l0 = __float2half(v0 - __half2float(h0));
                    __half h1 = __float2half(v1);
                    __half l1 = __float2half(v1 - __half2float(h1));
                    *reinterpret_cast<__half2*>(dh + jn)       = __halves2half2(h0, h1);
                    *reinterpret_cast<__half2*>(dh + HID + jn) = __halves2half2(l0, l1);
                }
            } else if (MODE == 2) {
                float* d = g_sh + (size_t)r * DIM;
#pragma unroll
                for (int nj = 0; nj < 8; nj++) {
                    int cl = wn * 64 + nj * 8 + lc;
                    float2 v;
                    v.x = acc[mi][nj][2 * h]     + bp[cl];
                    v.y = acc[mi][nj][2 * h + 1] + bp[cl + 1];
                    *reinterpret_cast<float2*>(d + bn * 128 + cl) = v;
                }
            } else {
                float* d = g_moe + (size_t)t * DIM;
#pragma unroll
                for (int nj = 0; nj < 8; nj++) {
                    int cl = wn * 64 + nj * 8 + lc;
                    float v0 = acc[mi][nj][2 * h]     + bp[cl];
                    float v1 = acc[mi][nj][2 * h + 1] + bp[cl + 1];
                    atomicAdd(d + bn * 128 + cl,     gw * v0);
                    atomicAdd(d + bn * 128 + cl + 1, gw * v1);
                }
            }
        }
    }
}

// ---------------- final mix -------------------------------------------------
__global__ void combine_kernel(const float* __restrict__ alpha,
                               const float* __restrict__ beta,
                               float* __restrict__ out) {
    float a = *alpha, b = *beta;
    float m  = fmaxf(a, b);
    float ea = expf(a - m), eb = expf(b - m);
    float inv = 1.0f / (ea + eb);
    float w0 = ea * inv, w1 = eb * inv;
    const int n = T_TOK * DIM;
    for (int i = blockIdx.x * blockDim.x + threadIdx.x; i < n;
         i += gridDim.x * blockDim.x)
        out[i] = w0 * g_sh[i] + w1 * g_moe[i];
}

// ---------------- launch ----------------------------------------------------
extern "C" void kernel_launch(void* const* d_in, const int* in_sizes, int n_in,
                              void* d_out, int out_size) {
    const float* x     = (const float*)d_in[0];
    const float* noise = (const float*)d_in[1];
    const float* Wr    = (const float*)d_in[2];
    const float* br    = (const float*)d_in[3];
    const float* W1    = (const float*)d_in[4];
    const float* b1    = (const float*)d_in[5];
    const float* W2    = (const float*)d_in[6];
    const float* b2    = (const float*)d_in[7];
    const float* Ws1   = (const float*)d_in[8];
    const float* bs1   = (const float*)d_in[9];
    const float* Ws2   = (const float*)d_in[10];
    const float* bs2   = (const float*)d_in[11];
    const float* alpha = (const float*)d_in[12];
    const float* beta  = (const float*)d_in[13];
    float* out = (float*)d_out;

    const int SMEM = 2 * 18432 + 2 * 10240;   // 57344
    cudaFuncSetAttribute(mma_gemm<0>, cudaFuncAttributeMaxDynamicSharedMemorySize, SMEM);
    cudaFuncSetAttribute(mma_gemm<1>, cudaFuncAttributeMaxDynamicSharedMemorySize, SMEM);
    cudaFuncSetAttribute(mma_gemm<2>, cudaFuncAttributeMaxDynamicSharedMemorySize, SMEM);
    cudaFuncSetAttribute(mma_gemm<3>, cudaFuncAttributeMaxDynamicSharedMemorySize, SMEM);

    zero_kernel<<<512, 256>>>();
    router_kernel<<<T_TOK / 4, 128>>>(x, noise, Wr, br);
    prep_x_kernel<<<(T_TOK * DIM + 255) / 256, 256>>>(x);
    prep_w_kernel<<<dim3(HID / 32, DIM / 32, 1),    dim3(32, 8)>>>(Ws1, 0, DIM, HID);
    prep_w_kernel<<<dim3(DIM / 32, HID / 32, 1),    dim3(32, 8)>>>(Ws2, 1, HID, DIM);
    prep_w_kernel<<<dim3(HID / 32, DIM / 32, NEXP), dim3(32, 8)>>>(W1, 2, DIM, HID);
    prep_w_kernel<<<dim3(DIM / 32, HID / 32, NEXP), dim3(32, 8)>>>(W2, 3, HID, DIM);
    // layer 1
    mma_gemm<1><<<dim3(HID / 128, T_TOK / 128, NEXP), 256, SMEM>>>(b1);
    mma_gemm<0><<<dim3(HID / 128, T_TOK / 128, 1),    256, SMEM>>>(bs1);
    // layer 2
    mma_gemm<3><<<dim3(DIM / 128, T_TOK / 128, NEXP), 256, SMEM>>>(b2);
    mma_gemm<2><<<dim3(DIM / 128, T_TOK / 128, 1),    256, SMEM>>>(bs2);
    combine_kernel<<<1536, 256>>>(alpha, beta, out);
}

// round 6
// speedup vs baseline: 4.6535x; 1.7051x over previous
#include <cuda_runtime.h>
#include <cuda_fp16.h>
#include <cstdint>

#define T_TOK 2048
#define DIM   768
#define HID   3072
#define NEXP  8

// ---------------- scratch (device globals) ----------------------------------
__device__ int   g_cnt[NEXP];
__device__ int   g_plist[NEXP * T_TOK];
__device__ float g_pw[2 * T_TOK];
__device__ float g_moe[T_TOK * DIM];
__device__ float g_sh[T_TOK * DIM];

__device__ __align__(16) __half g_x  [(size_t)T_TOK * DIM];         // fp16 x
__device__ __align__(16) __half g_hs [(size_t)T_TOK * HID];         // shared hidden
__device__ __align__(16) __half g_h  [(size_t)2 * T_TOK * HID];     // moe hidden (row=pair)
__device__ __align__(16) __half g_w1t [(size_t)NEXP * HID * DIM];   // W^T fp16 [N,K]
__device__ __align__(16) __half g_ws1t[(size_t)HID * DIM];
__device__ __align__(16) __half g_w2t [(size_t)NEXP * DIM * HID];
__device__ __align__(16) __half g_ws2t[(size_t)DIM * HID];

// ---------------- helpers ----------------------------------------------------
__device__ __forceinline__ uint32_t smem_u32(const void* p) {
    uint32_t a;
    asm("{ .reg .u64 t; cvta.to.shared.u64 t, %1; cvt.u32.u64 %0, t; }"
        : "=r"(a) : "l"(p));
    return a;
}
#define CP16(saddr, gptr) \
    asm volatile("cp.async.cg.shared.global [%0], [%1], 16;" \
                 :: "r"(saddr), "l"(gptr) : "memory")
#define CP_COMMIT() asm volatile("cp.async.commit_group;" ::: "memory")
template <int N>
__device__ __forceinline__ void cp_wait() {
    asm volatile("cp.async.wait_group %0;" :: "n"(N) : "memory");
}
#define LDM_X4(r, addr) \
    asm volatile("ldmatrix.sync.aligned.m8n8.x4.shared.b16 {%0,%1,%2,%3}, [%4];" \
                 : "=r"((r)[0]), "=r"((r)[1]), "=r"((r)[2]), "=r"((r)[3]) \
                 : "r"(addr))
__device__ __forceinline__ void mma16816(float* d, const uint32_t* a,
                                         uint32_t b0, uint32_t b1) {
    asm volatile(
        "mma.sync.aligned.m16n8k16.row.col.f32.f16.f16.f32 "
        "{%0,%1,%2,%3}, {%4,%5,%6,%7}, {%8,%9}, {%0,%1,%2,%3};"
        : "+f"(d[0]), "+f"(d[1]), "+f"(d[2]), "+f"(d[3])
        : "r"(a[0]), "r"(a[1]), "r"(a[2]), "r"(a[3]), "r"(b0), "r"(b1));
}

// ---------------- zero scratch ----------------------------------------------
__global__ void zero_kernel() {
    int i = blockIdx.x * blockDim.x + threadIdx.x;
    if (i < NEXP) g_cnt[i] = 0;
    const int n = T_TOK * DIM;
    for (int j = i; j < n; j += gridDim.x * blockDim.x) g_moe[j] = 0.0f;
}

// ---------------- router: one warp per token --------------------------------
__global__ void router_kernel(const float* __restrict__ x,
                              const float* __restrict__ noise,
                              const float* __restrict__ Wr,
                              const float* __restrict__ br) {
    int warp = (blockIdx.x * blockDim.x + threadIdx.x) >> 5;
    int lane = threadIdx.x & 31;
    if (warp >= T_TOK) return;
    const float* xr = x + warp * DIM;
    float acc[8] = {0.f, 0.f, 0.f, 0.f, 0.f, 0.f, 0.f, 0.f};
    for (int j = lane; j < DIM; j += 32) {
        float xv = xr[j];
        const float4* w4 = reinterpret_cast<const float4*>(Wr + j * NEXP);
        float4 wa = w4[0], wb = w4[1];
        acc[0] += xv * wa.x; acc[1] += xv * wa.y;
        acc[2] += xv * wa.z; acc[3] += xv * wa.w;
        acc[4] += xv * wb.x; acc[5] += xv * wb.y;
        acc[6] += xv * wb.z; acc[7] += xv * wb.w;
    }
#pragma unroll
    for (int off = 16; off; off >>= 1)
#pragma unroll
        for (int e = 0; e < 8; e++)
            acc[e] += __shfl_xor_sync(0xffffffffu, acc[e], off);
    if (lane == 0) {
        float lg[8];
#pragma unroll
        for (int e = 0; e < 8; e++)
            lg[e] = acc[e] + br[e] + 0.1f * noise[warp * NEXP + e];
        int i0 = 0;
#pragma unroll
        for (int e = 1; e < 8; e++) if (lg[e] > lg[i0]) i0 = e;
        int i1 = (i0 == 0) ? 1 : 0;
#pragma unroll
        for (int e = 0; e < 8; e++) if (e != i0 && lg[e] > lg[i1]) i1 = e;
        float e1 = expf(lg[i1] - lg[i0]);
        float w0 = 1.0f / (1.0f + e1);
        g_pw[2 * warp]     = w0;
        g_pw[2 * warp + 1] = e1 * w0;
        int p0 = atomicAdd(&g_cnt[i0], 1);
        g_plist[i0 * T_TOK + p0] = 2 * warp;
        int p1 = atomicAdd(&g_cnt[i1], 1);
        g_plist[i1 * T_TOK + p1] = 2 * warp + 1;
    }
}

// ---------------- prep: x -> fp16 (vectorized) ------------------------------
__global__ void prep_x_kernel(const float* __restrict__ x) {
    int i = blockIdx.x * blockDim.x + threadIdx.x;   // over float4s
    const int n4 = T_TOK * DIM / 4;
    if (i >= n4) return;
    float4 v = reinterpret_cast<const float4*>(x)[i];
    __half2 h0 = __floats2half2_rn(v.x, v.y);
    __half2 h1 = __floats2half2_rn(v.z, v.w);
    uint2 pk;
    pk.x = *reinterpret_cast<uint32_t*>(&h0);
    pk.y = *reinterpret_cast<uint32_t*>(&h1);
    reinterpret_cast<uint2*>(g_x)[i] = pk;
}

// ---------------- prep: W[K,N] fp32 -> WT[N,K] fp16, 64x64 tiles ------------
__global__ void prep_w_kernel(const float* __restrict__ W, int which, int K, int N) {
    int mat = blockIdx.z;
    W += (size_t)mat * K * N;
    __half* dst;
    switch (which) {
        case 0: dst = g_ws1t; break;
        case 1: dst = g_ws2t; break;
        case 2: dst = g_w1t + (size_t)mat * HID * DIM; break;
        default: dst = g_w2t + (size_t)mat * DIM * HID; break;
    }
    __shared__ float ts[64][68];
    const int n0 = blockIdx.x * 64, k0 = blockIdx.y * 64;
    const int tid = threadIdx.x;
    const int lrow = tid >> 2, lc4 = tid & 3;
#pragma unroll
    for (int j = 0; j < 4; j++) {
        float4 v = *reinterpret_cast<const float4*>(
            W + (size_t)(k0 + lrow) * N + n0 + (lc4 + 4 * j) * 4);
        *reinterpret_cast<float4*>(&ts[lrow][(lc4 + 4 * j) * 4]) = v;
    }
    __syncthreads();
    const int n = tid >> 2, kp = tid & 3;
    __half* d = dst + (size_t)(n0 + n) * K + k0 + kp * 16;
#pragma unroll
    for (int h = 0; h < 2; h++) {
        __half tmp[8];
#pragma unroll
        for (int j = 0; j < 8; j++)
            tmp[j] = __float2half(ts[kp * 16 + h * 8 + j][n]);
        *reinterpret_cast<uint4*>(d + h * 8) = *reinterpret_cast<uint4*>(tmp);
    }
}

// ---------------- HMMA GEMM fp16: D[128,128] = A[128,K] x B[128,K]^T --------
// block 128x128, 8 warps 4(M)x2(N), warp tile 32x64, K-chunk 32.
// smem rows padded to 80B -> conflict-free ldmatrix.
// MODE 0: shared L1  A=g_x           B=g_ws1t   -> g_hs (leaky)
// MODE 1: moe    L1  A=g_x (gather)  B=g_w1t[e] -> g_h  (leaky)
// MODE 2: shared L2  A=g_hs          B=g_ws2t   -> g_sh
// MODE 3: moe    L2  A=g_h (gather)  B=g_w2t[e] -> atomic g_moe
template <int MODE>
__global__ __launch_bounds__(256)
void mma_gemm(const float* __restrict__ bias) {
    constexpr int K = (MODE <= 1) ? DIM : HID;
    constexpr int S = K / 32;
    constexpr int BUFB = 10240;   // 128 rows * 80B

    const int bn = blockIdx.x, bm = blockIdx.y;
    int e = 0, M = T_TOK;
    if (MODE == 1 || MODE == 3) {
        e = blockIdx.z;
        M = g_cnt[e];
        if (bm * 128 >= M) return;
    }

    const __half* A;
    const __half* B;
    if (MODE == 0) { A = g_x;  B = g_ws1t; }
    if (MODE == 1) { A = g_x;  B = g_w1t + (size_t)e * HID * DIM; }
    if (MODE == 2) { A = g_hs; B = g_ws2t; }
    if (MODE == 3) { A = g_h;  B = g_w2t + (size_t)e * DIM * HID; }
    const __half* Bp = B + (size_t)(bn * 128) * K;
    const float* bp = bias + ((MODE == 1) ? e * HID : (MODE == 3) ? e * DIM : 0)
                    + bn * 128;

    __shared__ __align__(16) char sm_a[2][BUFB];
    __shared__ __align__(16) char sm_b[2][BUFB];
    __shared__ int plist_s[128];

    const int tid = threadIdx.x;
    const int lid = tid & 31, wid = tid >> 5;
    const int wm = wid >> 1, wn = wid & 1;

    if (MODE == 1 || MODE == 3) {
        if (tid < 128) {
            int r = bm * 128 + tid;
            plist_s[tid] = (r < M) ? g_plist[e * T_TOK + r] : -1;
        }
        __syncthreads();
    }

    // ---- per-thread cp.async mapping: 2 threads per row, 32B each ----
    const int lrow = tid >> 1;
    const int c4   = (tid & 1) * 2;      // 16B units
    const __half* arow;
    if (MODE == 0)      arow = g_x  + (size_t)(bm * 128 + lrow) * K;
    else if (MODE == 2) arow = g_hs + (size_t)(bm * 128 + lrow) * K;
    else {
        int p  = plist_s[lrow];
        int rr = (p >= 0) ? ((MODE == 1) ? (p >> 1) : p) : 0;
        arow = ((MODE == 1) ? g_x : g_h) + (size_t)rr * K;
    }
    const __half* brow = Bp + (size_t)lrow * K;
    arow += c4 * 8;
    brow += c4 * 8;
    const uint32_t sa0 = smem_u32(sm_a[0]) + lrow * 80 + c4 * 16;
    const uint32_t sb0 = smem_u32(sm_b[0]) + lrow * 80 + c4 * 16;

    // ---- ldmatrix base addresses ----
    const uint32_t aBase = smem_u32(sm_a[0])
        + (wm * 32 + ((lid >> 3) & 1) * 8 + (lid & 7)) * 80
        + (((lid >> 4) & 1) * 8) * 2;
    const uint32_t bBase = smem_u32(sm_b[0])
        + (wn * 64 + ((lid >> 4) & 1) * 8 + (lid & 7)) * 80
        + (((lid >> 3) & 1) * 8) * 2;

    float acc[2][8][4];
#pragma unroll
    for (int i = 0; i < 2; i++)
#pragma unroll
        for (int j = 0; j < 8; j++)
#pragma unroll
            for (int k = 0; k < 4; k++) acc[i][j][k] = 0.0f;

    // ---- prologue: stage 0 ----
    {
        CP16(sa0,      arow);
        CP16(sa0 + 16, arow + 8);
        CP16(sb0,      brow);
        CP16(sb0 + 16, brow + 8);
        CP_COMMIT();
    }

    for (int s = 0; s < S; ++s) {
        const int buf = s & 1;
        if (s + 1 < S) {
            const __half* ga = arow + (s + 1) * 32;
            const __half* gb = brow + (s + 1) * 32;
            const uint32_t da = sa0 + (buf ^ 1) * BUFB;
            const uint32_t db = sb0 + (buf ^ 1) * BUFB;
            CP16(da,      ga);
            CP16(da + 16, ga + 8);
            CP16(db,      gb);
            CP16(db + 16, gb + 8);
            CP_COMMIT();
            cp_wait<1>();
        } else {
            cp_wait<0>();
        }
        __syncthreads();

        const uint32_t ab = buf * BUFB;
#pragma unroll
        for (int kk = 0; kk < 32; kk += 16) {
            uint32_t af[2][4], bf[4][4];
#pragma unroll
            for (int mi = 0; mi < 2; mi++)
                LDM_X4(af[mi], aBase + ab + mi * 16 * 80 + kk * 2);
#pragma unroll
            for (int g = 0; g < 4; g++)
                LDM_X4(bf[g], bBase + ab + g * 16 * 80 + kk * 2);
#pragma unroll
            for (int mi = 0; mi < 2; mi++)
#pragma unroll
                for (int g = 0; g < 4; g++) {
                    mma16816(acc[mi][2 * g],     af[mi], bf[g][0], bf[g][1]);
                    mma16816(acc[mi][2 * g + 1], af[mi], bf[g][2], bf[g][3]);
                }
        }
        __syncthreads();
    }

    // ---- epilogue ----
    const int lr = lid >> 2;
    const int lc = (lid & 3) * 2;
#pragma unroll
    for (int mi = 0; mi < 2; mi++) {
#pragma unroll
        for (int h = 0; h < 2; h++) {
            int rl = wm * 32 + mi * 16 + h * 8 + lr;
            int r  = bm * 128 + rl;
            int p = 0, t = 0;
            float gw = 0.f;
            if (MODE == 1 || MODE == 3) {
                p = plist_s[rl];
                if (p < 0) continue;
                t = p >> 1;
                gw = g_pw[p];
            }
            if (MODE == 0 || MODE == 1) {
                __half* dh = (MODE == 0)
                    ? (g_hs + (size_t)r * HID)
                    : (g_h  + (size_t)p * HID);
#pragma unroll
                for (int nj = 0; nj < 8; nj++) {
                    int cl = wn * 64 + nj * 8 + lc;
                    int jn = bn * 128 + cl;
                    float v0 = acc[mi][nj][2 * h]     + bp[cl];
                    float v1 = acc[mi][nj][2 * h + 1] + bp[cl + 1];
                    v0 = (v0 > 0.f) ? v0 : 0.01f * v0;
                    v1 = (v1 > 0.f) ? v1 : 0.01f * v1;
                    *reinterpret_cast<__half2*>(dh + jn) =
                        __floats2half2_rn(v0, v1);
                }
            } else if (MODE == 2) {
                float* d = g_sh + (size_t)r * DIM;
#pragma unroll
                for (int nj = 0; nj < 8; nj++) {
                    int cl = wn * 64 + nj * 8 + lc;
                    float2 v;
                    v.x = acc[mi][nj][2 * h]     + bp[cl];
                    v.y = acc[mi][nj][2 * h + 1] + bp[cl + 1];
                    *reinterpret_cast<float2*>(d + bn * 128 + cl) = v;
                }
            } else {
                float* d = g_moe + (size_t)t * DIM;
#pragma unroll
                for (int nj = 0; nj < 8; nj++) {
                    int cl = wn * 64 + nj * 8 + lc;
                    float v0 = acc[mi][nj][2 * h]     + bp[cl];
                    float v1 = acc[mi][nj][2 * h + 1] + bp[cl + 1];
                    atomicAdd(d + bn * 128 + cl,     gw * v0);
                    atomicAdd(d + bn * 128 + cl + 1, gw * v1);
                }
            }
        }
    }
}

// ---------------- final mix -------------------------------------------------
__global__ void combine_kernel(const float* __restrict__ alpha,
                               const float* __restrict__ beta,
                               float* __restrict__ out) {
    float a = *alpha, b = *beta;
    float m  = fmaxf(a, b);
    float ea = expf(a - m), eb = expf(b - m);
    float inv = 1.0f / (ea + eb);
    float w0 = ea * inv, w1 = eb * inv;
    const int n = T_TOK * DIM;
    for (int i = blockIdx.x * blockDim.x + threadIdx.x; i < n;
         i += gridDim.x * blockDim.x)
        out[i] = w0 * g_sh[i] + w1 * g_moe[i];
}

// ---------------- launch ----------------------------------------------------
extern "C" void kernel_launch(void* const* d_in, const int* in_sizes, int n_in,
                              void* d_out, int out_size) {
    const float* x     = (const float*)d_in[0];
    const float* noise = (const float*)d_in[1];
    const float* Wr    = (const float*)d_in[2];
    const float* br    = (const float*)d_in[3];
    const float* W1    = (const float*)d_in[4];
    const float* b1    = (const float*)d_in[5];
    const float* W2    = (const float*)d_in[6];
    const float* b2    = (const float*)d_in[7];
    const float* Ws1   = (const float*)d_in[8];
    const float* bs1   = (const float*)d_in[9];
    const float* Ws2   = (const float*)d_in[10];
    const float* bs2   = (const float*)d_in[11];
    const float* alpha = (const float*)d_in[12];
    const float* beta  = (const float*)d_in[13];
    float* out = (float*)d_out;

    zero_kernel<<<512, 256>>>();
    router_kernel<<<T_TOK / 4, 128>>>(x, noise, Wr, br);
    prep_x_kernel<<<(T_TOK * DIM / 4 + 255) / 256, 256>>>(x);
    prep_w_kernel<<<dim3(HID / 64, DIM / 64, 1),    256>>>(Ws1, 0, DIM, HID);
    prep_w_kernel<<<dim3(DIM / 64, HID / 64, 1),    256>>>(Ws2, 1, HID, DIM);
    prep_w_kernel<<<dim3(HID / 64, DIM / 64, NEXP), 256>>>(W1, 2, DIM, HID);
    prep_w_kernel<<<dim3(DIM / 64, HID / 64, NEXP), 256>>>(W2, 3, HID, DIM);
    // layer 1
    mma_gemm<1><<<dim3(HID / 128, T_TOK / 128, NEXP), 256>>>(b1);
    mma_gemm<0><<<dim3(HID / 128, T_TOK / 128, 1),    256>>>(bs1);
    // layer 2
    mma_gemm<3><<<dim3(DIM / 128, T_TOK / 128, NEXP), 256>>>(b2);
    mma_gemm<2><<<dim3(DIM / 128, T_TOK / 128, 1),    256>>>(bs2);
    combine_kernel<<<1536, 256>>>(alpha, beta, out);
}

// round 7
// speedup vs baseline: 5.2715x; 1.1328x over previous
#include <cuda_runtime.h>
#include <cuda_fp16.h>
#include <cstdint>

#define T_TOK 2048
#define DIM   768
#define HID   3072
#define NEXP  8

// ---------------- scratch (device globals) ----------------------------------
__device__ int   g_cnt[NEXP];
__device__ int   g_plist[NEXP * T_TOK];
__device__ float g_pw[2 * T_TOK];
__device__ float g_moe[T_TOK * DIM];
__device__ float g_sh[T_TOK * DIM];

__device__ __align__(16) __half g_x  [(size_t)T_TOK * DIM];        // fp16 x
__device__ __align__(16) __half g_hs [(size_t)T_TOK * HID];        // shared hidden
__device__ __align__(16) __half g_h  [(size_t)2 * T_TOK * HID];    // moe hidden (row=pair)
__device__ __align__(16) __half g_w1h [(size_t)NEXP * DIM * HID];  // fp16, native [K,N]
__device__ __align__(16) __half g_ws1h[(size_t)DIM * HID];
__device__ __align__(16) __half g_w2h [(size_t)NEXP * HID * DIM];
__device__ __align__(16) __half g_ws2h[(size_t)HID * DIM];

// ---------------- helpers ----------------------------------------------------
__device__ __forceinline__ uint32_t smem_u32(const void* p) {
    uint32_t a;
    asm("{ .reg .u64 t; cvta.to.shared.u64 t, %1; cvt.u32.u64 %0, t; }"
        : "=r"(a) : "l"(p));
    return a;
}
#define CP16(saddr, gptr) \
    asm volatile("cp.async.cg.shared.global [%0], [%1], 16;" \
                 :: "r"(saddr), "l"(gptr) : "memory")
#define CP_COMMIT() asm volatile("cp.async.commit_group;" ::: "memory")
template <int N>
__device__ __forceinline__ void cp_wait() {
    asm volatile("cp.async.wait_group %0;" :: "n"(N) : "memory");
}
#define LDM_X4(r, addr) \
    asm volatile("ldmatrix.sync.aligned.m8n8.x4.shared.b16 {%0,%1,%2,%3}, [%4];" \
                 : "=r"((r)[0]), "=r"((r)[1]), "=r"((r)[2]), "=r"((r)[3]) \
                 : "r"(addr))
#define LDM_X4_T(r, addr) \
    asm volatile("ldmatrix.sync.aligned.m8n8.x4.trans.shared.b16 {%0,%1,%2,%3}, [%4];" \
                 : "=r"((r)[0]), "=r"((r)[1]), "=r"((r)[2]), "=r"((r)[3]) \
                 : "r"(addr))
__device__ __forceinline__ void mma16816(float* d, const uint32_t* a,
                                         uint32_t b0, uint32_t b1) {
    asm volatile(
        "mma.sync.aligned.m16n8k16.row.col.f32.f16.f16.f32 "
        "{%0,%1,%2,%3}, {%4,%5,%6,%7}, {%8,%9}, {%0,%1,%2,%3};"
        : "+f"(d[0]), "+f"(d[1]), "+f"(d[2]), "+f"(d[3])
        : "r"(a[0]), "r"(a[1]), "r"(a[2]), "r"(a[3]), "r"(b0), "r"(b1));
}

// ---------------- zero scratch ----------------------------------------------
__global__ void zero_kernel() {
    int i = blockIdx.x * blockDim.x + threadIdx.x;
    if (i < NEXP) g_cnt[i] = 0;
    const int n = T_TOK * DIM;
    for (int j = i; j < n; j += gridDim.x * blockDim.x) g_moe[j] = 0.0f;
}

// ---------------- router: one warp per token --------------------------------
__global__ void router_kernel(const float* __restrict__ x,
                              const float* __restrict__ noise,
                              const float* __restrict__ Wr,
                              const float* __restrict__ br) {
    int warp = (blockIdx.x * blockDim.x + threadIdx.x) >> 5;
    int lane = threadIdx.x & 31;
    if (warp >= T_TOK) return;
    const float* xr = x + warp * DIM;
    float acc[8] = {0.f, 0.f, 0.f, 0.f, 0.f, 0.f, 0.f, 0.f};
    for (int j = lane; j < DIM; j += 32) {
        float xv = xr[j];
        const float4* w4 = reinterpret_cast<const float4*>(Wr + j * NEXP);
        float4 wa = w4[0], wb = w4[1];
        acc[0] += xv * wa.x; acc[1] += xv * wa.y;
        acc[2] += xv * wa.z; acc[3] += xv * wa.w;
        acc[4] += xv * wb.x; acc[5] += xv * wb.y;
        acc[6] += xv * wb.z; acc[7] += xv * wb.w;
    }
#pragma unroll
    for (int off = 16; off; off >>= 1)
#pragma unroll
        for (int e = 0; e < 8; e++)
            acc[e] += __shfl_xor_sync(0xffffffffu, acc[e], off);
    if (lane == 0) {
        float lg[8];
#pragma unroll
        for (int e = 0; e < 8; e++)
            lg[e] = acc[e] + br[e] + 0.1f * noise[warp * NEXP + e];
        int i0 = 0;
#pragma unroll
        for (int e = 1; e < 8; e++) if (lg[e] > lg[i0]) i0 = e;
        int i1 = (i0 == 0) ? 1 : 0;
#pragma unroll
        for (int e = 0; e < 8; e++) if (e != i0 && lg[e] > lg[i1]) i1 = e;
        float e1 = expf(lg[i1] - lg[i0]);
        float w0 = 1.0f / (1.0f + e1);
        g_pw[2 * warp]     = w0;
        g_pw[2 * warp + 1] = e1 * w0;
        int p0 = atomicAdd(&g_cnt[i0], 1);
        g_plist[i0 * T_TOK + p0] = 2 * warp;
        int p1 = atomicAdd(&g_cnt[i1], 1);
        g_plist[i1 * T_TOK + p1] = 2 * warp + 1;
    }
}

// ---------------- prep: x -> fp16 (vectorized) ------------------------------
__global__ void prep_x_kernel(const float* __restrict__ x) {
    int i = blockIdx.x * blockDim.x + threadIdx.x;
    const int n4 = T_TOK * DIM / 4;
    if (i >= n4) return;
    float4 v = reinterpret_cast<const float4*>(x)[i];
    __half2 h0 = __floats2half2_rn(v.x, v.y);
    __half2 h1 = __floats2half2_rn(v.z, v.w);
    uint2 pk;
    pk.x = *reinterpret_cast<uint32_t*>(&h0);
    pk.y = *reinterpret_cast<uint32_t*>(&h1);
    reinterpret_cast<uint2*>(g_x)[i] = pk;
}

// ---------------- conv: fp32 -> fp16 streaming copy (native layout) ---------
__global__ void conv_w_kernel(const float4* __restrict__ src,
                              uint2* __restrict__ dst, int n4) {
    int i = blockIdx.x * blockDim.x + threadIdx.x;
    if (i >= n4) return;
    float4 v = src[i];
    __half2 h0 = __floats2half2_rn(v.x, v.y);
    __half2 h1 = __floats2half2_rn(v.z, v.w);
    uint2 pk;
    pk.x = *reinterpret_cast<uint32_t*>(&h0);
    pk.y = *reinterpret_cast<uint32_t*>(&h1);
    dst[i] = pk;
}

// ---------------- HMMA GEMM: D[128,128] = A[128,K] x W[K,N] tile ------------
// block 128x128, 8 warps 4(M)x2(N), warp tile 32x64, K-chunk 32.
// A smem: [row][k] 80B pitch (ldmatrix). B smem: [k][n] 272B pitch
// (ldmatrix.trans), weights consumed in NATIVE [K,N] layout.
// grid.z in [0,8]: z<8 => expert z (gathered rows, gated scatter on L2),
//                  z==8 => shared expert (dense rows).
template <int LAYER>   // 1 or 2
__global__ __launch_bounds__(256)
void mma_gemm(const float* __restrict__ bias_moe,
              const float* __restrict__ bias_sh) {
    constexpr int K = (LAYER == 1) ? DIM : HID;
    constexpr int N = (LAYER == 1) ? HID : DIM;
    constexpr int S = K / 32;
    constexpr int BUFA = 128 * 80;    // 10240
    constexpr int BUFB = 32 * 272;    // 8704

    const int bn = blockIdx.x, bm = blockIdx.y, e = blockIdx.z;
    const bool sh = (e == NEXP);
    const int M = sh ? T_TOK : g_cnt[e];
    if (bm * 128 >= M) return;

    const __half* Bg;
    const float* bp;
    if (LAYER == 1) {
        Bg = sh ? g_ws1h : g_w1h + (size_t)e * DIM * HID;
        bp = (sh ? bias_sh : bias_moe + e * HID) + bn * 128;
    } else {
        Bg = sh ? g_ws2h : g_w2h + (size_t)e * HID * DIM;
        bp = (sh ? bias_sh : bias_moe + e * DIM) + bn * 128;
    }
    Bg += bn * 128;

    __shared__ __align__(16) char sm_a[2][BUFA];
    __shared__ __align__(16) char sm_b[2][BUFB];
    __shared__ int plist_s[128];

    const int tid = threadIdx.x;
    const int lid = tid & 31, wid = tid >> 5;
    const int wm = wid >> 1, wn = wid & 1;

    if (!sh) {
        if (tid < 128) {
            int r = bm * 128 + tid;
            plist_s[tid] = (r < M) ? g_plist[e * T_TOK + tid + bm * 128] : -1;
        }
        __syncthreads();
    }

    // ---- A cp.async: 2 threads per row, 32B each ----
    const int lrow = tid >> 1;
    const int c4   = (tid & 1) * 2;
    const __half* arow;
    if (sh) {
        arow = ((LAYER == 1) ? g_x : g_hs) + (size_t)(bm * 128 + lrow) * K;
    } else {
        int p  = plist_s[lrow];
        int rr = (p >= 0) ? ((LAYER == 1) ? (p >> 1) : p) : 0;
        arow = ((LAYER == 1) ? g_x : g_h) + (size_t)rr * K;
    }
    arow += c4 * 8;
    const uint32_t sa0 = smem_u32(sm_a[0]) + lrow * 80 + c4 * 16;

    // ---- B cp.async: [k][n] rows, 272B pitch; 1 thread = 32B of one row ----
    const int brow_ = tid >> 3;           // 0..31 (k within chunk)
    const int bseg  = (tid & 7) * 2;      // 16B segments
    const __half* bgp = Bg + (size_t)brow_ * N + bseg * 8;
    const uint32_t sb0 = smem_u32(sm_b[0]) + brow_ * 272 + bseg * 16;

    // ---- ldmatrix bases ----
    const uint32_t aBase = smem_u32(sm_a[0])
        + (wm * 32 + ((lid >> 3) & 1) * 8 + (lid & 7)) * 80
        + (((lid >> 4) & 1) * 8) * 2;
    const int bmx = lid >> 3, brr = lid & 7;
    const uint32_t bBase = smem_u32(sm_b[0])
        + (brr + (bmx & 1) * 8) * 272
        + (wn * 64 + (bmx >> 1) * 8) * 2;

    float acc[2][8][4];
#pragma unroll
    for (int i = 0; i < 2; i++)
#pragma unroll
        for (int j = 0; j < 8; j++)
#pragma unroll
            for (int k = 0; k < 4; k++) acc[i][j][k] = 0.0f;

    // ---- prologue ----
    {
        CP16(sa0,      arow);
        CP16(sa0 + 16, arow + 8);
        CP16(sb0,      bgp);
        CP16(sb0 + 16, bgp + 8);
        CP_COMMIT();
    }

    for (int s = 0; s < S; ++s) {
        const int buf = s & 1;
        if (s + 1 < S) {
            const __half* ga = arow + (s + 1) * 32;
            const __half* gb = bgp + (size_t)(s + 1) * 32 * N;
            const uint32_t da = sa0 + (buf ^ 1) * BUFA;
            const uint32_t db = sb0 + (buf ^ 1) * BUFB;
            CP16(da,      ga);
            CP16(da + 16, ga + 8);
            CP16(db,      gb);
            CP16(db + 16, gb + 8);
            CP_COMMIT();
            cp_wait<1>();
        } else {
            cp_wait<0>();
        }
        __syncthreads();

        const uint32_t ab = buf * BUFA;
        const uint32_t bb = buf * BUFB;
#pragma unroll
        for (int kk = 0; kk < 32; kk += 16) {
            uint32_t af[2][4], bt[4][4];
#pragma unroll
            for (int mi = 0; mi < 2; mi++)
                LDM_X4(af[mi], aBase + ab + mi * 16 * 80 + kk * 2);
#pragma unroll
            for (int g = 0; g < 4; g++)
                LDM_X4_T(bt[g], bBase + bb + kk * 272 + g * 32);
#pragma unroll
            for (int mi = 0; mi < 2; mi++)
#pragma unroll
                for (int g = 0; g < 4; g++) {
                    mma16816(acc[mi][2 * g],     af[mi], bt[g][0], bt[g][1]);
                    mma16816(acc[mi][2 * g + 1], af[mi], bt[g][2], bt[g][3]);
                }
        }
        __syncthreads();
    }

    // ---- epilogue ----
    const int lr = lid >> 2;
    const int lc = (lid & 3) * 2;
#pragma unroll
    for (int mi = 0; mi < 2; mi++) {
#pragma unroll
        for (int h = 0; h < 2; h++) {
            int rl = wm * 32 + mi * 16 + h * 8 + lr;
            int r  = bm * 128 + rl;
            int p = 0, t = 0;
            float gw = 0.f;
            if (!sh) {
                p = plist_s[rl];
                if (p < 0) continue;
                t = p >> 1;
                gw = g_pw[p];
            }
            if (LAYER == 1) {
                __half* dh = sh ? (g_hs + (size_t)r * HID)
                                : (g_h  + (size_t)p * HID);
#pragma unroll
                for (int nj = 0; nj < 8; nj++) {
                    int cl = wn * 64 + nj * 8 + lc;
                    float v0 = acc[mi][nj][2 * h]     + bp[cl];
                    float v1 = acc[mi][nj][2 * h + 1] + bp[cl + 1];
                    v0 = (v0 > 0.f) ? v0 : 0.01f * v0;
                    v1 = (v1 > 0.f) ? v1 : 0.01f * v1;
                    *reinterpret_cast<__half2*>(dh + bn * 128 + cl) =
                        __floats2half2_rn(v0, v1);
                }
            } else if (sh) {
                float* d = g_sh + (size_t)r * DIM;
#pragma unroll
                for (int nj = 0; nj < 8; nj++) {
                    int cl = wn * 64 + nj * 8 + lc;
                    float2 v;
                    v.x = acc[mi][nj][2 * h]     + bp[cl];
                    v.y = acc[mi][nj][2 * h + 1] + bp[cl + 1];
                    *reinterpret_cast<float2*>(d + bn * 128 + cl) = v;
                }
            } else {
                float* d = g_moe + (size_t)t * DIM;
#pragma unroll
                for (int nj = 0; nj < 8; nj++) {
                    int cl = wn * 64 + nj * 8 + lc;
                    float v0 = acc[mi][nj][2 * h]     + bp[cl];
                    float v1 = acc[mi][nj][2 * h + 1] + bp[cl + 1];
                    atomicAdd(d + bn * 128 + cl,     gw * v0);
                    atomicAdd(d + bn * 128 + cl + 1, gw * v1);
                }
            }
        }
    }
}

// ---------------- final mix -------------------------------------------------
__global__ void combine_kernel(const float* __restrict__ alpha,
                               const float* __restrict__ beta,
                               float* __restrict__ out) {
    float a = *alpha, b = *beta;
    float m  = fmaxf(a, b);
    float ea = expf(a - m), eb = expf(b - m);
    float inv = 1.0f / (ea + eb);
    float w0 = ea * inv, w1 = eb * inv;
    const int n = T_TOK * DIM;
    for (int i = blockIdx.x * blockDim.x + threadIdx.x; i < n;
         i += gridDim.x * blockDim.x)
        out[i] = w0 * g_sh[i] + w1 * g_moe[i];
}

// ---------------- launch ----------------------------------------------------
extern "C" void kernel_launch(void* const* d_in, const int* in_sizes, int n_in,
                              void* d_out, int out_size) {
    const float* x     = (const float*)d_in[0];
    const float* noise = (const float*)d_in[1];
    const float* Wr    = (const float*)d_in[2];
    const float* br    = (const float*)d_in[3];
    const float* W1    = (const float*)d_in[4];
    const float* b1    = (const float*)d_in[5];
    const float* W2    = (const float*)d_in[6];
    const float* b2    = (const float*)d_in[7];
    const float* Ws1   = (const float*)d_in[8];
    const float* bs1   = (const float*)d_in[9];
    const float* Ws2   = (const float*)d_in[10];
    const float* bs2   = (const float*)d_in[11];
    const float* alpha = (const float*)d_in[12];
    const float* beta  = (const float*)d_in[13];
    float* out = (float*)d_out;

    __half* w1h;  cudaGetSymbolAddress((void**)&w1h,  g_w1h);
    __half* w2h;  cudaGetSymbolAddress((void**)&w2h,  g_w2h);
    __half* ws1h; cudaGetSymbolAddress((void**)&ws1h, g_ws1h);
    __half* ws2h; cudaGetSymbolAddress((void**)&ws2h, g_ws2h);

    zero_kernel<<<512, 256>>>();
    router_kernel<<<T_TOK / 4, 128>>>(x, noise, Wr, br);
    prep_x_kernel<<<(T_TOK * DIM / 4 + 255) / 256, 256>>>(x);

    const int nW  = NEXP * DIM * HID / 4;
    const int nWs = DIM * HID / 4;
    conv_w_kernel<<<(nW  + 255) / 256, 256>>>((const float4*)W1,  (uint2*)w1h,  nW);
    conv_w_kernel<<<(nW  + 255) / 256, 256>>>((const float4*)W2,  (uint2*)w2h,  nW);
    conv_w_kernel<<<(nWs + 255) / 256, 256>>>((const float4*)Ws1, (uint2*)ws1h, nWs);
    conv_w_kernel<<<(nWs + 255) / 256, 256>>>((const float4*)Ws2, (uint2*)ws2h, nWs);

    mma_gemm<1><<<dim3(HID / 128, T_TOK / 128, NEXP + 1), 256>>>(b1, bs1);
    mma_gemm<2><<<dim3(DIM / 128, T_TOK / 128, NEXP + 1), 256>>>(b2, bs2);
    combine_kernel<<<1536, 256>>>(alpha, beta, out);
}

// round 8
// speedup vs baseline: 5.4680x; 1.0373x over previous
#include <cuda_runtime.h>
#include <cuda_fp16.h>
#include <cstdint>

#define T_TOK 2048
#define DIM   768
#define HID   3072
#define NEXP  8

// ---------------- scratch (device globals) ----------------------------------
__device__ int   g_cnt[NEXP];
__device__ int   g_plist[NEXP * T_TOK];
__device__ float g_pw[2 * T_TOK];
__device__ float g_moe[T_TOK * DIM];
__device__ float g_sh[T_TOK * DIM];

__device__ __align__(16) __half g_x  [(size_t)T_TOK * DIM];
__device__ __align__(16) __half g_hs [(size_t)T_TOK * HID];
__device__ __align__(16) __half g_h  [(size_t)2 * T_TOK * HID];
__device__ __align__(16) __half g_w1h [(size_t)NEXP * DIM * HID];  // native [K,N]
__device__ __align__(16) __half g_ws1h[(size_t)DIM * HID];
__device__ __align__(16) __half g_w2h [(size_t)NEXP * HID * DIM];
__device__ __align__(16) __half g_ws2h[(size_t)HID * DIM];

// ---------------- helpers ----------------------------------------------------
__device__ __forceinline__ uint32_t smem_u32(const void* p) {
    uint32_t a;
    asm("{ .reg .u64 t; cvta.to.shared.u64 t, %1; cvt.u32.u64 %0, t; }"
        : "=r"(a) : "l"(p));
    return a;
}
#define CP16(saddr, gptr) \
    asm volatile("cp.async.cg.shared.global [%0], [%1], 16;" \
                 :: "r"(saddr), "l"(gptr) : "memory")
#define CP_COMMIT() asm volatile("cp.async.commit_group;" ::: "memory")
template <int N>
__device__ __forceinline__ void cp_wait() {
    asm volatile("cp.async.wait_group %0;" :: "n"(N) : "memory");
}
#define LDM_X4(r, addr) \
    asm volatile("ldmatrix.sync.aligned.m8n8.x4.shared.b16 {%0,%1,%2,%3}, [%4];" \
                 : "=r"((r)[0]), "=r"((r)[1]), "=r"((r)[2]), "=r"((r)[3]) \
                 : "r"(addr))
#define LDM_X4_T(r, addr) \
    asm volatile("ldmatrix.sync.aligned.m8n8.x4.trans.shared.b16 {%0,%1,%2,%3}, [%4];" \
                 : "=r"((r)[0]), "=r"((r)[1]), "=r"((r)[2]), "=r"((r)[3]) \
                 : "r"(addr))
__device__ __forceinline__ void mma16816(float* d, const uint32_t* a,
                                         uint32_t b0, uint32_t b1) {
    asm volatile(
        "mma.sync.aligned.m16n8k16.row.col.f32.f16.f16.f32 "
        "{%0,%1,%2,%3}, {%4,%5,%6,%7}, {%8,%9}, {%0,%1,%2,%3};"
        : "+f"(d[0]), "+f"(d[1]), "+f"(d[2]), "+f"(d[3])
        : "r"(a[0]), "r"(a[1]), "r"(a[2]), "r"(a[3]), "r"(b0), "r"(b1));
}

// ---------------- zero scratch ----------------------------------------------
__global__ void zero_kernel() {
    int i = blockIdx.x * blockDim.x + threadIdx.x;
    if (i < NEXP) g_cnt[i] = 0;
    const int n = T_TOK * DIM;
    for (int j = i; j < n; j += gridDim.x * blockDim.x) g_moe[j] = 0.0f;
}

// ---------------- router: one warp per token --------------------------------
__global__ void router_kernel(const float* __restrict__ x,
                              const float* __restrict__ noise,
                              const float* __restrict__ Wr,
                              const float* __restrict__ br) {
    int warp = (blockIdx.x * blockDim.x + threadIdx.x) >> 5;
    int lane = threadIdx.x & 31;
    if (warp >= T_TOK) return;
    const float* xr = x + warp * DIM;
    float acc[8] = {0.f, 0.f, 0.f, 0.f, 0.f, 0.f, 0.f, 0.f};
    for (int j = lane; j < DIM; j += 32) {
        float xv = xr[j];
        const float4* w4 = reinterpret_cast<const float4*>(Wr + j * NEXP);
        float4 wa = w4[0], wb = w4[1];
        acc[0] += xv * wa.x; acc[1] += xv * wa.y;
        acc[2] += xv * wa.z; acc[3] += xv * wa.w;
        acc[4] += xv * wb.x; acc[5] += xv * wb.y;
        acc[6] += xv * wb.z; acc[7] += xv * wb.w;
    }
#pragma unroll
    for (int off = 16; off; off >>= 1)
#pragma unroll
        for (int e = 0; e < 8; e++)
            acc[e] += __shfl_xor_sync(0xffffffffu, acc[e], off);
    if (lane == 0) {
        float lg[8];
#pragma unroll
        for (int e = 0; e < 8; e++)
            lg[e] = acc[e] + br[e] + 0.1f * noise[warp * NEXP + e];
        int i0 = 0;
#pragma unroll
        for (int e = 1; e < 8; e++) if (lg[e] > lg[i0]) i0 = e;
        int i1 = (i0 == 0) ? 1 : 0;
#pragma unroll
        for (int e = 0; e < 8; e++) if (e != i0 && lg[e] > lg[i1]) i1 = e;
        float e1 = expf(lg[i1] - lg[i0]);
        float w0 = 1.0f / (1.0f + e1);
        g_pw[2 * warp]     = w0;
        g_pw[2 * warp + 1] = e1 * w0;
        int p0 = atomicAdd(&g_cnt[i0], 1);
        g_plist[i0 * T_TOK + p0] = 2 * warp;
        int p1 = atomicAdd(&g_cnt[i1], 1);
        g_plist[i1 * T_TOK + p1] = 2 * warp + 1;
    }
}

// ---------------- prep: x -> fp16 -------------------------------------------
__global__ void prep_x_kernel(const float* __restrict__ x) {
    int i = blockIdx.x * blockDim.x + threadIdx.x;
    const int n4 = T_TOK * DIM / 4;
    if (i >= n4) return;
    float4 v = reinterpret_cast<const float4*>(x)[i];
    __half2 h0 = __floats2half2_rn(v.x, v.y);
    __half2 h1 = __floats2half2_rn(v.z, v.w);
    uint2 pk;
    pk.x = *reinterpret_cast<uint32_t*>(&h0);
    pk.y = *reinterpret_cast<uint32_t*>(&h1);
    reinterpret_cast<uint2*>(g_x)[i] = pk;
}

// ---------------- conv: fp32 -> fp16 streaming copy --------------------------
__global__ void conv_w_kernel(const float4* __restrict__ src,
                              uint2* __restrict__ dst, int n4) {
    int i = blockIdx.x * blockDim.x + threadIdx.x;
    if (i >= n4) return;
    float4 v = src[i];
    __half2 h0 = __floats2half2_rn(v.x, v.y);
    __half2 h1 = __floats2half2_rn(v.z, v.w);
    uint2 pk;
    pk.x = *reinterpret_cast<uint32_t*>(&h0);
    pk.y = *reinterpret_cast<uint32_t*>(&h1);
    dst[i] = pk;
}

// ---------------- HMMA GEMM, 3-stage cp.async ring ---------------------------
// block 128x128, 8 warps 4(M)x2(N), warp tile 32x64, K-chunk 32.
// A smem: [row][k] 80B pitch; B smem: [k][n] 272B pitch (native [K,N] weights,
// consumed via ldmatrix.trans). One __syncthreads per K-chunk.
// grid.z: z<8 => expert z (gathered rows, gated scatter on L2); z==8 => shared.
template <int LAYER>
__global__ __launch_bounds__(256)
void mma_gemm(const float* __restrict__ bias_moe,
              const float* __restrict__ bias_sh) {
    constexpr int K = (LAYER == 1) ? DIM : HID;
    constexpr int N = (LAYER == 1) ? HID : DIM;
    constexpr int S = K / 32;
    constexpr int BUFA = 128 * 80;    // 10240
    constexpr int BUFB = 32 * 272;    // 8704

    const int bn = blockIdx.x, bm = blockIdx.y, e = blockIdx.z;
    const bool sh = (e == NEXP);
    const int M = sh ? T_TOK : g_cnt[e];
    if (bm * 128 >= M) return;

    const __half* Bg;
    const float* bp;
    if (LAYER == 1) {
        Bg = sh ? g_ws1h : g_w1h + (size_t)e * DIM * HID;
        bp = (sh ? bias_sh : bias_moe + e * HID) + bn * 128;
    } else {
        Bg = sh ? g_ws2h : g_w2h + (size_t)e * HID * DIM;
        bp = (sh ? bias_sh : bias_moe + e * DIM) + bn * 128;
    }
    Bg += bn * 128;

    extern __shared__ __align__(16) char dsm[];
    char* sm_a = dsm;                 // 3 x BUFA
    char* sm_b = dsm + 3 * BUFA;      // 3 x BUFB
    __shared__ int plist_s[128];

    const int tid = threadIdx.x;
    const int lid = tid & 31, wid = tid >> 5;
    const int wm = wid >> 1, wn = wid & 1;

    if (!sh) {
        if (tid < 128) {
            int r = bm * 128 + tid;
            plist_s[tid] = (r < M) ? g_plist[e * T_TOK + tid + bm * 128] : -1;
        }
        __syncthreads();
    }

    // ---- A cp.async: 2 threads per row, 32B each ----
    const int lrow = tid >> 1;
    const int c4   = (tid & 1) * 2;
    const __half* arow;
    if (sh) {
        arow = ((LAYER == 1) ? g_x : g_hs) + (size_t)(bm * 128 + lrow) * K;
    } else {
        int p  = plist_s[lrow];
        int rr = (p >= 0) ? ((LAYER == 1) ? (p >> 1) : p) : 0;
        arow = ((LAYER == 1) ? g_x : g_h) + (size_t)rr * K;
    }
    arow += c4 * 8;
    const uint32_t sa0 = smem_u32(sm_a) + lrow * 80 + c4 * 16;

    // ---- B cp.async: [k][n] rows, 272B pitch ----
    const int brow_ = tid >> 3;
    const int bseg  = (tid & 7) * 2;
    const __half* bgp = Bg + (size_t)brow_ * N + bseg * 8;
    const uint32_t sb0 = smem_u32(sm_b) + brow_ * 272 + bseg * 16;

    // ---- ldmatrix bases ----
    const uint32_t aBase = smem_u32(sm_a)
        + (wm * 32 + ((lid >> 3) & 1) * 8 + (lid & 7)) * 80
        + (((lid >> 4) & 1) * 8) * 2;
    const int bmx = lid >> 3, brr = lid & 7;
    const uint32_t bBase = smem_u32(sm_b)
        + (brr + (bmx & 1) * 8) * 272
        + (wn * 64 + (bmx >> 1) * 8) * 2;

    float acc[2][8][4];
#pragma unroll
    for (int i = 0; i < 2; i++)
#pragma unroll
        for (int j = 0; j < 8; j++)
#pragma unroll
            for (int k = 0; k < 4; k++) acc[i][j][k] = 0.0f;

    auto load_stage = [&](int st) {
        const __half* ga = arow + st * 32;
        const __half* gb = bgp + (size_t)st * 32 * N;
        const uint32_t da = sa0 + (st % 3) * BUFA;
        const uint32_t db = sb0 + (st % 3) * BUFB;
        CP16(da,      ga);
        CP16(da + 16, ga + 8);
        CP16(db,      gb);
        CP16(db + 16, gb + 8);
    };

    // ---- prologue: stages 0, 1 ----
    load_stage(0); CP_COMMIT();
    load_stage(1); CP_COMMIT();

    for (int s = 0; s < S; ++s) {
        cp_wait<1>();
        __syncthreads();
        if (s + 2 < S) load_stage(s + 2);
        CP_COMMIT();

        const uint32_t ab = (s % 3) * BUFA;
        const uint32_t bb = (s % 3) * BUFB;
#pragma unroll
        for (int kk = 0; kk < 32; kk += 16) {
            uint32_t af[2][4], bt[4][4];
#pragma unroll
            for (int mi = 0; mi < 2; mi++)
                LDM_X4(af[mi], aBase + ab + mi * 16 * 80 + kk * 2);
#pragma unroll
            for (int g = 0; g < 4; g++)
                LDM_X4_T(bt[g], bBase + bb + kk * 272 + g * 32);
#pragma unroll
            for (int mi = 0; mi < 2; mi++)
#pragma unroll
                for (int g = 0; g < 4; g++) {
                    mma16816(acc[mi][2 * g],     af[mi], bt[g][0], bt[g][1]);
                    mma16816(acc[mi][2 * g + 1], af[mi], bt[g][2], bt[g][3]);
                }
        }
    }

    // ---- epilogue ----
    const int lr = lid >> 2;
    const int lc = (lid & 3) * 2;
#pragma unroll
    for (int mi = 0; mi < 2; mi++) {
#pragma unroll
        for (int h = 0; h < 2; h++) {
            int rl = wm * 32 + mi * 16 + h * 8 + lr;
            int r  = bm * 128 + rl;
            int p = 0, t = 0;
            float gw = 0.f;
            if (!sh) {
                p = plist_s[rl];
                if (p < 0) continue;
                t = p >> 1;
                gw = g_pw[p];
            }
            if (LAYER == 1) {
                __half* dh = sh ? (g_hs + (size_t)r * HID)
                                : (g_h  + (size_t)p * HID);
#pragma unroll
                for (int nj = 0; nj < 8; nj++) {
                    int cl = wn * 64 + nj * 8 + lc;
                    float v0 = acc[mi][nj][2 * h]     + bp[cl];
                    float v1 = acc[mi][nj][2 * h + 1] + bp[cl + 1];
                    v0 = (v0 > 0.f) ? v0 : 0.01f * v0;
                    v1 = (v1 > 0.f) ? v1 : 0.01f * v1;
                    *reinterpret_cast<__half2*>(dh + bn * 128 + cl) =
                        __floats2half2_rn(v0, v1);
                }
            } else if (sh) {
                float* d = g_sh + (size_t)r * DIM;
#pragma unroll
                for (int nj = 0; nj < 8; nj++) {
                    int cl = wn * 64 + nj * 8 + lc;
                    float2 v;
                    v.x = acc[mi][nj][2 * h]     + bp[cl];
                    v.y = acc[mi][nj][2 * h + 1] + bp[cl + 1];
                    *reinterpret_cast<float2*>(d + bn * 128 + cl) = v;
                }
            } else {
                float* d = g_moe + (size_t)t * DIM;
#pragma unroll
                for (int nj = 0; nj < 8; nj++) {
                    int cl = wn * 64 + nj * 8 + lc;
                    float v0 = acc[mi][nj][2 * h]     + bp[cl];
                    float v1 = acc[mi][nj][2 * h + 1] + bp[cl + 1];
                    atomicAdd(d + bn * 128 + cl,     gw * v0);
                    atomicAdd(d + bn * 128 + cl + 1, gw * v1);
                }
            }
        }
    }
}

// ---------------- final mix -------------------------------------------------
__global__ void combine_kernel(const float* __restrict__ alpha,
                               const float* __restrict__ beta,
                               float* __restrict__ out) {
    float a = *alpha, b = *beta;
    float m  = fmaxf(a, b);
    float ea = expf(a - m), eb = expf(b - m);
    float inv = 1.0f / (ea + eb);
    float w0 = ea * inv, w1 = eb * inv;
    const int n = T_TOK * DIM;
    for (int i = blockIdx.x * blockDim.x + threadIdx.x; i < n;
         i += gridDim.x * blockDim.x)
        out[i] = w0 * g_sh[i] + w1 * g_moe[i];
}

// ---------------- launch ----------------------------------------------------
extern "C" void kernel_launch(void* const* d_in, const int* in_sizes, int n_in,
                              void* d_out, int out_size) {
    const float* x     = (const float*)d_in[0];
    const float* noise = (const float*)d_in[1];
    const float* Wr    = (const float*)d_in[2];
    const float* br    = (const float*)d_in[3];
    const float* W1    = (const float*)d_in[4];
    const float* b1    = (const float*)d_in[5];
    const float* W2    = (const float*)d_in[6];
    const float* b2    = (const float*)d_in[7];
    const float* Ws1   = (const float*)d_in[8];
    const float* bs1   = (const float*)d_in[9];
    const float* Ws2   = (const float*)d_in[10];
    const float* bs2   = (const float*)d_in[11];
    const float* alpha = (const float*)d_in[12];
    const float* beta  = (const float*)d_in[13];
    float* out = (float*)d_out;

    __half* w1h;  cudaGetSymbolAddress((void**)&w1h,  g_w1h);
    __half* w2h;  cudaGetSymbolAddress((void**)&w2h,  g_w2h);
    __half* ws1h; cudaGetSymbolAddress((void**)&ws1h, g_ws1h);
    __half* ws2h; cudaGetSymbolAddress((void**)&ws2h, g_ws2h);

    const int SMEM = 3 * 10240 + 3 * 8704;   // 56832
    cudaFuncSetAttribute(mma_gemm<1>, cudaFuncAttributeMaxDynamicSharedMemorySize, SMEM);
    cudaFuncSetAttribute(mma_gemm<2>, cudaFuncAttributeMaxDynamicSharedMemorySize, SMEM);

    // fork two side streams for weight conversion (graph-capture-safe pattern)
    cudaStream_t st1, st2;
    cudaStreamCreateWithFlags(&st1, cudaStreamNonBlocking);
    cudaStreamCreateWithFlags(&st2, cudaStreamNonBlocking);
    cudaEvent_t evRoot, ev1, ev2;
    cudaEventCreateWithFlags(&evRoot, cudaEventDisableTiming);
    cudaEventCreateWithFlags(&ev1,    cudaEventDisableTiming);
    cudaEventCreateWithFlags(&ev2,    cudaEventDisableTiming);

    cudaEventRecord(evRoot, 0);
    cudaStreamWaitEvent(st1, evRoot, 0);
    cudaStreamWaitEvent(st2, evRoot, 0);

    const int nW  = NEXP * DIM * HID / 4;
    const int nWs = DIM * HID / 4;
    // side stream 1: layer-1 weights
    conv_w_kernel<<<(nW  + 255) / 256, 256, 0, st1>>>((const float4*)W1,  (uint2*)w1h,  nW);
    conv_w_kernel<<<(nWs + 255) / 256, 256, 0, st1>>>((const float4*)Ws1, (uint2*)ws1h, nWs);
    cudaEventRecord(ev1, st1);
    // side stream 2: layer-2 weights (hidden under GEMM1)
    conv_w_kernel<<<(nW  + 255) / 256, 256, 0, st2>>>((const float4*)W2,  (uint2*)w2h,  nW);
    conv_w_kernel<<<(nWs + 255) / 256, 256, 0, st2>>>((const float4*)Ws2, (uint2*)ws2h, nWs);
    cudaEventRecord(ev2, st2);

    // main stream: routing + x prep overlap conv W1
    zero_kernel<<<512, 256>>>();
    router_kernel<<<T_TOK / 4, 128>>>(x, noise, Wr, br);
    prep_x_kernel<<<(T_TOK * DIM / 4 + 255) / 256, 256>>>(x);

    cudaStreamWaitEvent(0, ev1, 0);
    mma_gemm<1><<<dim3(HID / 128, T_TOK / 128, NEXP + 1), 256, SMEM>>>(b1, bs1);
    cudaStreamWaitEvent(0, ev2, 0);
    mma_gemm<2><<<dim3(DIM / 128, T_TOK / 128, NEXP + 1), 256, SMEM>>>(b2, bs2);
    combine_kernel<<<1536, 256>>>(alpha, beta, out);

    cudaEventDestroy(evRoot);
    cudaEventDestroy(ev1);
    cudaEventDestroy(ev2);
    cudaStreamDestroy(st1);
    cudaStreamDestroy(st2);
}

// round 9
// speedup vs baseline: 5.5051x; 1.0068x over previous
#include <cuda_runtime.h>
#include <cuda_fp16.h>
#include <cstdint>

#define T_TOK 2048
#define DIM   768
#define HID   3072
#define NEXP  8

// ---------------- scratch (device globals) ----------------------------------
__device__ int   g_cnt[NEXP];
__device__ int   g_plist[NEXP * T_TOK];
__device__ float g_pw[2 * T_TOK];
__device__ float g_moe2[(size_t)2 * T_TOK * DIM];   // per-pair L2 output (no atomics)
__device__ float g_sh[T_TOK * DIM];

__device__ __align__(16) __half g_x  [(size_t)T_TOK * DIM];
__device__ __align__(16) __half g_hs [(size_t)T_TOK * HID];
__device__ __align__(16) __half g_h  [(size_t)2 * T_TOK * HID];
__device__ __align__(16) __half g_w1h [(size_t)NEXP * DIM * HID];  // native [K,N]
__device__ __align__(16) __half g_ws1h[(size_t)DIM * HID];
__device__ __align__(16) __half g_w2h [(size_t)NEXP * HID * DIM];
__device__ __align__(16) __half g_ws2h[(size_t)HID * DIM];

// ---------------- helpers ----------------------------------------------------
__device__ __forceinline__ uint32_t smem_u32(const void* p) {
    uint32_t a;
    asm("{ .reg .u64 t; cvta.to.shared.u64 t, %1; cvt.u32.u64 %0, t; }"
        : "=r"(a) : "l"(p));
    return a;
}
#define CP16(saddr, gptr) \
    asm volatile("cp.async.cg.shared.global [%0], [%1], 16;" \
                 :: "r"(saddr), "l"(gptr) : "memory")
#define CP_COMMIT() asm volatile("cp.async.commit_group;" ::: "memory")
template <int N>
__device__ __forceinline__ void cp_wait() {
    asm volatile("cp.async.wait_group %0;" :: "n"(N) : "memory");
}
#define LDM_X4(r, addr) \
    asm volatile("ldmatrix.sync.aligned.m8n8.x4.shared.b16 {%0,%1,%2,%3}, [%4];" \
                 : "=r"((r)[0]), "=r"((r)[1]), "=r"((r)[2]), "=r"((r)[3]) \
                 : "r"(addr))
#define LDM_X4_T(r, addr) \
    asm volatile("ldmatrix.sync.aligned.m8n8.x4.trans.shared.b16 {%0,%1,%2,%3}, [%4];" \
                 : "=r"((r)[0]), "=r"((r)[1]), "=r"((r)[2]), "=r"((r)[3]) \
                 : "r"(addr))
__device__ __forceinline__ void mma16816(float* d, const uint32_t* a,
                                         uint32_t b0, uint32_t b1) {
    asm volatile(
        "mma.sync.aligned.m16n8k16.row.col.f32.f16.f16.f32 "
        "{%0,%1,%2,%3}, {%4,%5,%6,%7}, {%8,%9}, {%0,%1,%2,%3};"
        : "+f"(d[0]), "+f"(d[1]), "+f"(d[2]), "+f"(d[3])
        : "r"(a[0]), "r"(a[1]), "r"(a[2]), "r"(a[3]), "r"(b0), "r"(b1));
}

// ---------------- zero counters only ----------------------------------------
__global__ void zero_kernel() {
    if (threadIdx.x < NEXP) g_cnt[threadIdx.x] = 0;
}

// ---------------- router: one warp per token --------------------------------
__global__ void router_kernel(const float* __restrict__ x,
                              const float* __restrict__ noise,
                              const float* __restrict__ Wr,
                              const float* __restrict__ br) {
    int warp = (blockIdx.x * blockDim.x + threadIdx.x) >> 5;
    int lane = threadIdx.x & 31;
    if (warp >= T_TOK) return;
    const float* xr = x + warp * DIM;
    float acc[8] = {0.f, 0.f, 0.f, 0.f, 0.f, 0.f, 0.f, 0.f};
    for (int j = lane; j < DIM; j += 32) {
        float xv = xr[j];
        const float4* w4 = reinterpret_cast<const float4*>(Wr + j * NEXP);
        float4 wa = w4[0], wb = w4[1];
        acc[0] += xv * wa.x; acc[1] += xv * wa.y;
        acc[2] += xv * wa.z; acc[3] += xv * wa.w;
        acc[4] += xv * wb.x; acc[5] += xv * wb.y;
        acc[6] += xv * wb.z; acc[7] += xv * wb.w;
    }
#pragma unroll
    for (int off = 16; off; off >>= 1)
#pragma unroll
        for (int e = 0; e < 8; e++)
            acc[e] += __shfl_xor_sync(0xffffffffu, acc[e], off);
    if (lane == 0) {
        float lg[8];
#pragma unroll
        for (int e = 0; e < 8; e++)
            lg[e] = acc[e] + br[e] + 0.1f * noise[warp * NEXP + e];
        int i0 = 0;
#pragma unroll
        for (int e = 1; e < 8; e++) if (lg[e] > lg[i0]) i0 = e;
        int i1 = (i0 == 0) ? 1 : 0;
#pragma unroll
        for (int e = 0; e < 8; e++) if (e != i0 && lg[e] > lg[i1]) i1 = e;
        float e1 = expf(lg[i1] - lg[i0]);
        float w0 = 1.0f / (1.0f + e1);
        g_pw[2 * warp]     = w0;
        g_pw[2 * warp + 1] = e1 * w0;
        int p0 = atomicAdd(&g_cnt[i0], 1);
        g_plist[i0 * T_TOK + p0] = 2 * warp;
        int p1 = atomicAdd(&g_cnt[i1], 1);
        g_plist[i1 * T_TOK + p1] = 2 * warp + 1;
    }
}

// ---------------- prep: x -> fp16 -------------------------------------------
__global__ void prep_x_kernel(const float* __restrict__ x) {
    int i = blockIdx.x * blockDim.x + threadIdx.x;
    const int n4 = T_TOK * DIM / 4;
    if (i >= n4) return;
    float4 v = reinterpret_cast<const float4*>(x)[i];
    __half2 h0 = __floats2half2_rn(v.x, v.y);
    __half2 h1 = __floats2half2_rn(v.z, v.w);
    uint2 pk;
    pk.x = *reinterpret_cast<uint32_t*>(&h0);
    pk.y = *reinterpret_cast<uint32_t*>(&h1);
    reinterpret_cast<uint2*>(g_x)[i] = pk;
}

// ---------------- conv: expert + shared weights of one layer ------------------
__global__ void conv_w_kernel(const float4* __restrict__ srcE,
                              uint2* __restrict__ dstE, int nE,
                              const float4* __restrict__ srcS,
                              uint2* __restrict__ dstS, int nS) {
    int i = blockIdx.x * blockDim.x + threadIdx.x;
    const float4* src;
    uint2* dst;
    if (i < nE) { src = srcE; dst = dstE; }
    else if (i < nE + nS) { src = srcS - nE; dst = dstS - nE; }
    else return;
    float4 v = src[i];
    __half2 h0 = __floats2half2_rn(v.x, v.y);
    __half2 h1 = __floats2half2_rn(v.z, v.w);
    uint2 pk;
    pk.x = *reinterpret_cast<uint32_t*>(&h0);
    pk.y = *reinterpret_cast<uint32_t*>(&h1);
    dst[i] = pk;
}

// ---------------- HMMA GEMM, 3-stage cp.async ring ---------------------------
// block 128x128, 8 warps 4(M)x2(N), warp tile 32x64, K-chunk 32.
// A smem: [row][k] 80B pitch; B smem: [k][n] 272B pitch (native [K,N] weights,
// ldmatrix.trans). One __syncthreads per K-chunk.
// grid.z: z<8 => expert z (gathered rows); z==8 => shared expert (dense).
template <int LAYER>
__global__ __launch_bounds__(256)
void mma_gemm(const float* __restrict__ bias_moe,
              const float* __restrict__ bias_sh) {
    constexpr int K = (LAYER == 1) ? DIM : HID;
    constexpr int N = (LAYER == 1) ? HID : DIM;
    constexpr int S = K / 32;
    constexpr int BUFA = 128 * 80;    // 10240
    constexpr int BUFB = 32 * 272;    // 8704

    const int bn = blockIdx.x, bm = blockIdx.y, e = blockIdx.z;
    const bool sh = (e == NEXP);
    const int M = sh ? T_TOK : g_cnt[e];
    if (bm * 128 >= M) return;

    const __half* Bg;
    const float* bp;
    if (LAYER == 1) {
        Bg = sh ? g_ws1h : g_w1h + (size_t)e * DIM * HID;
        bp = (sh ? bias_sh : bias_moe + e * HID) + bn * 128;
    } else {
        Bg = sh ? g_ws2h : g_w2h + (size_t)e * HID * DIM;
        bp = (sh ? bias_sh : bias_moe + e * DIM) + bn * 128;
    }
    Bg += bn * 128;

    extern __shared__ __align__(16) char dsm[];
    char* sm_a = dsm;                 // 3 x BUFA
    char* sm_b = dsm + 3 * BUFA;      // 3 x BUFB
    __shared__ int plist_s[128];

    const int tid = threadIdx.x;
    const int lid = tid & 31, wid = tid >> 5;
    const int wm = wid >> 1, wn = wid & 1;

    if (!sh) {
        if (tid < 128) {
            int r = bm * 128 + tid;
            plist_s[tid] = (r < M) ? g_plist[e * T_TOK + tid + bm * 128] : -1;
        }
        __syncthreads();
    }

    // ---- A cp.async: 2 threads per row, 32B each ----
    const int lrow = tid >> 1;
    const int c4   = (tid & 1) * 2;
    const __half* arow;
    if (sh) {
        arow = ((LAYER == 1) ? g_x : g_hs) + (size_t)(bm * 128 + lrow) * K;
    } else {
        int p  = plist_s[lrow];
        int rr = (p >= 0) ? ((LAYER == 1) ? (p >> 1) : p) : 0;
        arow = ((LAYER == 1) ? g_x : g_h) + (size_t)rr * K;
    }
    arow += c4 * 8;
    const uint32_t sa0 = smem_u32(sm_a) + lrow * 80 + c4 * 16;

    // ---- B cp.async: [k][n] rows, 272B pitch ----
    const int brow_ = tid >> 3;
    const int bseg  = (tid & 7) * 2;
    const __half* bgp = Bg + (size_t)brow_ * N + bseg * 8;
    const uint32_t sb0 = smem_u32(sm_b) + brow_ * 272 + bseg * 16;

    // ---- ldmatrix bases ----
    const uint32_t aBase = smem_u32(sm_a)
        + (wm * 32 + ((lid >> 3) & 1) * 8 + (lid & 7)) * 80
        + (((lid >> 4) & 1) * 8) * 2;
    const int bmx = lid >> 3, brr = lid & 7;
    const uint32_t bBase = smem_u32(sm_b)
        + (brr + (bmx & 1) * 8) * 272
        + (wn * 64 + (bmx >> 1) * 8) * 2;

    float acc[2][8][4];
#pragma unroll
    for (int i = 0; i < 2; i++)
#pragma unroll
        for (int j = 0; j < 8; j++)
#pragma unroll
            for (int k = 0; k < 4; k++) acc[i][j][k] = 0.0f;

    auto load_stage = [&](int st) {
        const __half* ga = arow + st * 32;
        const __half* gb = bgp + (size_t)st * 32 * N;
        const uint32_t da = sa0 + (st % 3) * BUFA;
        const uint32_t db = sb0 + (st % 3) * BUFB;
        CP16(da,      ga);
        CP16(da + 16, ga + 8);
        CP16(db,      gb);
        CP16(db + 16, gb + 8);
    };

    load_stage(0); CP_COMMIT();
    load_stage(1); CP_COMMIT();

    for (int s = 0; s < S; ++s) {
        cp_wait<1>();
        __syncthreads();
        if (s + 2 < S) load_stage(s + 2);
        CP_COMMIT();

        const uint32_t ab = (s % 3) * BUFA;
        const uint32_t bb = (s % 3) * BUFB;
#pragma unroll
        for (int kk = 0; kk < 32; kk += 16) {
            uint32_t af[2][4], bt[4][4];
#pragma unroll
            for (int mi = 0; mi < 2; mi++)
                LDM_X4(af[mi], aBase + ab + mi * 16 * 80 + kk * 2);
#pragma unroll
            for (int g = 0; g < 4; g++)
                LDM_X4_T(bt[g], bBase + bb + kk * 272 + g * 32);
#pragma unroll
            for (int mi = 0; mi < 2; mi++)
#pragma unroll
                for (int g = 0; g < 4; g++) {
                    mma16816(acc[mi][2 * g],     af[mi], bt[g][0], bt[g][1]);
                    mma16816(acc[mi][2 * g + 1], af[mi], bt[g][2], bt[g][3]);
                }
        }
    }

    // ---- epilogue ----
    const int lr = lid >> 2;
    const int lc = (lid & 3) * 2;
#pragma unroll
    for (int mi = 0; mi < 2; mi++) {
#pragma unroll
        for (int h = 0; h < 2; h++) {
            int rl = wm * 32 + mi * 16 + h * 8 + lr;
            int r  = bm * 128 + rl;
            int p = 0;
            float gw = 0.f;
            if (!sh) {
                p = plist_s[rl];
                if (p < 0) continue;
                gw = g_pw[p];
            }
            if (LAYER == 1) {
                __half* dh = sh ? (g_hs + (size_t)r * HID)
                                : (g_h  + (size_t)p * HID);
#pragma unroll
                for (int nj = 0; nj < 8; nj++) {
                    int cl = wn * 64 + nj * 8 + lc;
                    float v0 = acc[mi][nj][2 * h]     + bp[cl];
                    float v1 = acc[mi][nj][2 * h + 1] + bp[cl + 1];
                    v0 = (v0 > 0.f) ? v0 : 0.01f * v0;
                    v1 = (v1 > 0.f) ? v1 : 0.01f * v1;
                    *reinterpret_cast<__half2*>(dh + bn * 128 + cl) =
                        __floats2half2_rn(v0, v1);
                }
            } else if (sh) {
                float* d = g_sh + (size_t)r * DIM;
#pragma unroll
                for (int nj = 0; nj < 8; nj++) {
                    int cl = wn * 64 + nj * 8 + lc;
                    float2 v;
                    v.x = acc[mi][nj][2 * h]     + bp[cl];
                    v.y = acc[mi][nj][2 * h + 1] + bp[cl + 1];
                    *reinterpret_cast<float2*>(d + bn * 128 + cl) = v;
                }
            } else {
                // plain gated store: each pair row is written exactly once
                float* d = g_moe2 + (size_t)p * DIM;
#pragma unroll
                for (int nj = 0; nj < 8; nj++) {
                    int cl = wn * 64 + nj * 8 + lc;
                    float2 v;
                    v.x = gw * (acc[mi][nj][2 * h]     + bp[cl]);
                    v.y = gw * (acc[mi][nj][2 * h + 1] + bp[cl + 1]);
                    *reinterpret_cast<float2*>(d + bn * 128 + cl) = v;
                }
            }
        }
    }
}

// ---------------- final mix -------------------------------------------------
__global__ void combine_kernel(const float* __restrict__ alpha,
                               const float* __restrict__ beta,
                               float* __restrict__ out) {
    float a = *alpha, b = *beta;
    float m  = fmaxf(a, b);
    float ea = expf(a - m), eb = expf(b - m);
    float inv = 1.0f / (ea + eb);
    float w0 = ea * inv, w1 = eb * inv;
    const int n = T_TOK * DIM;
    for (int i = blockIdx.x * blockDim.x + threadIdx.x; i < n;
         i += gridDim.x * blockDim.x) {
        int t = i / DIM, j = i % DIM;
        float moe = g_moe2[(size_t)(2 * t) * DIM + j]
                  + g_moe2[(size_t)(2 * t + 1) * DIM + j];
        out[i] = w0 * g_sh[i] + w1 * moe;
    }
}

// ---------------- launch ----------------------------------------------------
extern "C" void kernel_launch(void* const* d_in, const int* in_sizes, int n_in,
                              void* d_out, int out_size) {
    const float* x     = (const float*)d_in[0];
    const float* noise = (const float*)d_in[1];
    const float* Wr    = (const float*)d_in[2];
    const float* br    = (const float*)d_in[3];
    const float* W1    = (const float*)d_in[4];
    const float* b1    = (const float*)d_in[5];
    const float* W2    = (const float*)d_in[6];
    const float* b2    = (const float*)d_in[7];
    const float* Ws1   = (const float*)d_in[8];
    const float* bs1   = (const float*)d_in[9];
    const float* Ws2   = (const float*)d_in[10];
    const float* bs2   = (const float*)d_in[11];
    const float* alpha = (const float*)d_in[12];
    const float* beta  = (const float*)d_in[13];
    float* out = (float*)d_out;

    __half* w1h;  cudaGetSymbolAddress((void**)&w1h,  g_w1h);
    __half* w2h;  cudaGetSymbolAddress((void**)&w2h,  g_w2h);
    __half* ws1h; cudaGetSymbolAddress((void**)&ws1h, g_ws1h);
    __half* ws2h; cudaGetSymbolAddress((void**)&ws2h, g_ws2h);

    const int SMEM = 3 * 10240 + 3 * 8704;   // 56832
    cudaFuncSetAttribute(mma_gemm<1>, cudaFuncAttributeMaxDynamicSharedMemorySize, SMEM);
    cudaFuncSetAttribute(mma_gemm<2>, cudaFuncAttributeMaxDynamicSharedMemorySize, SMEM);

    cudaStream_t st1, st2;
    cudaStreamCreateWithFlags(&st1, cudaStreamNonBlocking);
    cudaStreamCreateWithFlags(&st2, cudaStreamNonBlocking);
    cudaEvent_t evRoot, ev1, ev2;
    cudaEventCreateWithFlags(&evRoot, cudaEventDisableTiming);
    cudaEventCreateWithFlags(&ev1,    cudaEventDisableTiming);
    cudaEventCreateWithFlags(&ev2,    cudaEventDisableTiming);

    const int nW  = NEXP * DIM * HID / 4;
    const int nWs = DIM * HID / 4;
    const int nTot = nW + nWs;

    // launches #0..#2 (main stream)
    zero_kernel<<<1, 32>>>();
    router_kernel<<<T_TOK / 4, 128>>>(x, noise, Wr, br);
    prep_x_kernel<<<(T_TOK * DIM / 4 + 255) / 256, 256>>>(x);

    cudaEventRecord(evRoot, 0);
    cudaStreamWaitEvent(st1, evRoot, 0);
    cudaStreamWaitEvent(st2, evRoot, 0);

    // launch #3: layer-1 weights (expert + shared fused)
    conv_w_kernel<<<(nTot + 255) / 256, 256, 0, st1>>>(
        (const float4*)W1, (uint2*)w1h, nW, (const float4*)Ws1, (uint2*)ws1h, nWs);
    cudaEventRecord(ev1, st1);
    // launch #4: layer-2 weights
    conv_w_kernel<<<(nTot + 255) / 256, 256, 0, st2>>>(
        (const float4*)W2, (uint2*)w2h, nW, (const float4*)Ws2, (uint2*)ws2h, nWs);
    cudaEventRecord(ev2, st2);

    // launch #5: GEMM1  (ncu -s 5 -c 1 captures this)
    cudaStreamWaitEvent(0, ev1, 0);
    mma_gemm<1><<<dim3(HID / 128, T_TOK / 128, NEXP + 1), 256, SMEM>>>(b1, bs1);
    cudaStreamWaitEvent(0, ev2, 0);
    mma_gemm<2><<<dim3(DIM / 128, T_TOK / 128, NEXP + 1), 256, SMEM>>>(b2, bs2);
    combine_kernel<<<1536, 256>>>(alpha, beta, out);

    cudaEventDestroy(evRoot);
    cudaEventDestroy(ev1);
    cudaEventDestroy(ev2);
    cudaStreamDestroy(st1);
    cudaStreamDestroy(st2);
}

// round 10
// speedup vs baseline: 5.9485x; 1.0805x over previous
#include <cuda_runtime.h>
#include <cuda_fp16.h>
#include <cstdint>

#define T_TOK 2048
#define DIM   768
#define HID   3072
#define NEXP  8

// ---------------- scratch (device globals) ----------------------------------
__device__ int   g_cnt[NEXP];
__device__ int   g_plist[NEXP * T_TOK];
__device__ float g_pw[2 * T_TOK];
__device__ float g_moe2[(size_t)2 * T_TOK * DIM];   // per-pair L2 output
__device__ float g_sh[T_TOK * DIM];

__device__ __align__(16) __half g_x  [(size_t)T_TOK * DIM];
__device__ __align__(16) __half g_hs [(size_t)T_TOK * HID];
__device__ __align__(16) __half g_h  [(size_t)2 * T_TOK * HID];
__device__ __align__(16) __half g_w1h [(size_t)NEXP * DIM * HID];  // native [K,N]
__device__ __align__(16) __half g_ws1h[(size_t)DIM * HID];
__device__ __align__(16) __half g_w2h [(size_t)NEXP * HID * DIM];
__device__ __align__(16) __half g_ws2h[(size_t)HID * DIM];

// ---------------- helpers ----------------------------------------------------
__device__ __forceinline__ uint32_t smem_u32(const void* p) {
    uint32_t a;
    asm("{ .reg .u64 t; cvta.to.shared.u64 t, %1; cvt.u32.u64 %0, t; }"
        : "=r"(a) : "l"(p));
    return a;
}
#define CP16(saddr, gptr) \
    asm volatile("cp.async.cg.shared.global [%0], [%1], 16;" \
                 :: "r"(saddr), "l"(gptr) : "memory")
#define CP_COMMIT() asm volatile("cp.async.commit_group;" ::: "memory")
template <int N>
__device__ __forceinline__ void cp_wait() {
    asm volatile("cp.async.wait_group %0;" :: "n"(N) : "memory");
}
#define LDM_X4(r, addr) \
    asm volatile("ldmatrix.sync.aligned.m8n8.x4.shared.b16 {%0,%1,%2,%3}, [%4];" \
                 : "=r"((r)[0]), "=r"((r)[1]), "=r"((r)[2]), "=r"((r)[3]) \
                 : "r"(addr))
#define LDM_X4_T(r, addr) \
    asm volatile("ldmatrix.sync.aligned.m8n8.x4.trans.shared.b16 {%0,%1,%2,%3}, [%4];" \
                 : "=r"((r)[0]), "=r"((r)[1]), "=r"((r)[2]), "=r"((r)[3]) \
                 : "r"(addr))
__device__ __forceinline__ void mma16816(float* d, const uint32_t* a,
                                         uint32_t b0, uint32_t b1) {
    asm volatile(
        "mma.sync.aligned.m16n8k16.row.col.f32.f16.f16.f32 "
        "{%0,%1,%2,%3}, {%4,%5,%6,%7}, {%8,%9}, {%0,%1,%2,%3};"
        : "+f"(d[0]), "+f"(d[1]), "+f"(d[2]), "+f"(d[3])
        : "r"(a[0]), "r"(a[1]), "r"(a[2]), "r"(a[3]), "r"(b0), "r"(b1));
}

// ---------------- zero counters ----------------------------------------------
__global__ void zero_kernel() {
    if (threadIdx.x < NEXP) g_cnt[threadIdx.x] = 0;
}

// ---------------- router: one warp per token --------------------------------
__global__ void router_kernel(const float* __restrict__ x,
                              const float* __restrict__ noise,
                              const float* __restrict__ Wr,
                              const float* __restrict__ br) {
    int warp = (blockIdx.x * blockDim.x + threadIdx.x) >> 5;
    int lane = threadIdx.x & 31;
    if (warp >= T_TOK) return;
    const float* xr = x + warp * DIM;
    float acc[8] = {0.f, 0.f, 0.f, 0.f, 0.f, 0.f, 0.f, 0.f};
    for (int j = lane; j < DIM; j += 32) {
        float xv = xr[j];
        const float4* w4 = reinterpret_cast<const float4*>(Wr + j * NEXP);
        float4 wa = w4[0], wb = w4[1];
        acc[0] += xv * wa.x; acc[1] += xv * wa.y;
        acc[2] += xv * wa.z; acc[3] += xv * wa.w;
        acc[4] += xv * wb.x; acc[5] += xv * wb.y;
        acc[6] += xv * wb.z; acc[7] += xv * wb.w;
    }
#pragma unroll
    for (int off = 16; off; off >>= 1)
#pragma unroll
        for (int e = 0; e < 8; e++)
            acc[e] += __shfl_xor_sync(0xffffffffu, acc[e], off);
    if (lane == 0) {
        float lg[8];
#pragma unroll
        for (int e = 0; e < 8; e++)
            lg[e] = acc[e] + br[e] + 0.1f * noise[warp * NEXP + e];
        int i0 = 0;
#pragma unroll
        for (int e = 1; e < 8; e++) if (lg[e] > lg[i0]) i0 = e;
        int i1 = (i0 == 0) ? 1 : 0;
#pragma unroll
        for (int e = 0; e < 8; e++) if (e != i0 && lg[e] > lg[i1]) i1 = e;
        float e1 = expf(lg[i1] - lg[i0]);
        float w0 = 1.0f / (1.0f + e1);
        g_pw[2 * warp]     = w0;
        g_pw[2 * warp + 1] = e1 * w0;
        int p0 = atomicAdd(&g_cnt[i0], 1);
        g_plist[i0 * T_TOK + p0] = 2 * warp;
        int p1 = atomicAdd(&g_cnt[i1], 1);
        g_plist[i1 * T_TOK + p1] = 2 * warp + 1;
    }
}

// ---------------- prep: x -> fp16 -------------------------------------------
__global__ void prep_x_kernel(const float* __restrict__ x) {
    int i = blockIdx.x * blockDim.x + threadIdx.x;
    const int n4 = T_TOK * DIM / 4;
    if (i >= n4) return;
    float4 v = reinterpret_cast<const float4*>(x)[i];
    __half2 h0 = __floats2half2_rn(v.x, v.y);
    __half2 h1 = __floats2half2_rn(v.z, v.w);
    uint2 pk;
    pk.x = *reinterpret_cast<uint32_t*>(&h0);
    pk.y = *reinterpret_cast<uint32_t*>(&h1);
    reinterpret_cast<uint2*>(g_x)[i] = pk;
}

// ---------------- conv: ALL weights in one launch ----------------------------
__global__ void conv_all_kernel(const float4* __restrict__ W1,
                                const float4* __restrict__ W2,
                                const float4* __restrict__ Ws1,
                                const float4* __restrict__ Ws2,
                                uint2* __restrict__ w1h,
                                uint2* __restrict__ w2h,
                                uint2* __restrict__ ws1h,
                                uint2* __restrict__ ws2h,
                                int nW, int nWs) {
    int i = blockIdx.x * blockDim.x + threadIdx.x;
    const float4* src;
    uint2* dst;
    int j;
    if (i < nW)                    { src = W1;  dst = w1h;  j = i; }
    else if (i < 2 * nW)           { src = W2;  dst = w2h;  j = i - nW; }
    else if (i < 2 * nW + nWs)     { src = Ws1; dst = ws1h; j = i - 2 * nW; }
    else if (i < 2 * nW + 2 * nWs) { src = Ws2; dst = ws2h; j = i - 2 * nW - nWs; }
    else return;
    float4 v = src[j];
    __half2 h0 = __floats2half2_rn(v.x, v.y);
    __half2 h1 = __floats2half2_rn(v.z, v.w);
    uint2 pk;
    pk.x = *reinterpret_cast<uint32_t*>(&h0);
    pk.y = *reinterpret_cast<uint32_t*>(&h1);
    dst[j] = pk;
}

// ---------------- HMMA GEMM, 3-stage cp.async ring, forced occ=2 -------------
// block 128x128, 8 warps 4(M)x2(N), warp tile 32x64, K-chunk 32.
// A smem: [row][k] 80B pitch; B smem: [k][n] 272B pitch (native [K,N] weights,
// ldmatrix.trans). One __syncthreads per K-chunk.
// grid.z: z<8 => expert z (gathered rows); z==8 => shared expert (dense).
template <int LAYER>
__global__ __launch_bounds__(256, 2)
void mma_gemm(const float* __restrict__ bias_moe,
              const float* __restrict__ bias_sh) {
    constexpr int K = (LAYER == 1) ? DIM : HID;
    constexpr int N = (LAYER == 1) ? HID : DIM;
    constexpr int S = K / 32;
    constexpr int BUFA = 128 * 80;    // 10240
    constexpr int BUFB = 32 * 272;    // 8704

    const int bn = blockIdx.x, bm = blockIdx.y, e = blockIdx.z;
    const bool sh = (e == NEXP);
    const int M = sh ? T_TOK : g_cnt[e];
    if (bm * 128 >= M) return;

    const __half* Bg;
    const float* bp;
    if (LAYER == 1) {
        Bg = sh ? g_ws1h : g_w1h + (size_t)e * DIM * HID;
        bp = (sh ? bias_sh : bias_moe + e * HID) + bn * 128;
    } else {
        Bg = sh ? g_ws2h : g_w2h + (size_t)e * HID * DIM;
        bp = (sh ? bias_sh : bias_moe + e * DIM) + bn * 128;
    }
    Bg += bn * 128;

    extern __shared__ __align__(16) char dsm[];
    char* sm_a = dsm;                 // 3 x BUFA
    char* sm_b = dsm + 3 * BUFA;      // 3 x BUFB
    __shared__ int plist_s[128];

    const int tid = threadIdx.x;
    const int lid = tid & 31, wid = tid >> 5;
    const int wm = wid >> 1, wn = wid & 1;

    if (!sh) {
        if (tid < 128) {
            int r = bm * 128 + tid;
            plist_s[tid] = (r < M) ? g_plist[e * T_TOK + tid + bm * 128] : -1;
        }
        __syncthreads();
    }

    // ---- A cp.async: 2 threads per row, 32B each ----
    const int lrow = tid >> 1;
    const int c4   = (tid & 1) * 2;
    const __half* arow;
    if (sh) {
        arow = ((LAYER == 1) ? g_x : g_hs) + (size_t)(bm * 128 + lrow) * K;
    } else {
        int p  = plist_s[lrow];
        int rr = (p >= 0) ? ((LAYER == 1) ? (p >> 1) : p) : 0;
        arow = ((LAYER == 1) ? g_x : g_h) + (size_t)rr * K;
    }
    arow += c4 * 8;
    const uint32_t sa0 = smem_u32(sm_a) + lrow * 80 + c4 * 16;

    // ---- B cp.async: [k][n] rows, 272B pitch ----
    const int brow_ = tid >> 3;
    const int bseg  = (tid & 7) * 2;
    const __half* bgp = Bg + (size_t)brow_ * N + bseg * 8;
    const uint32_t sb0 = smem_u32(sm_b) + brow_ * 272 + bseg * 16;

    // ---- ldmatrix bases ----
    const uint32_t aBase = smem_u32(sm_a)
        + (wm * 32 + ((lid >> 3) & 1) * 8 + (lid & 7)) * 80
        + (((lid >> 4) & 1) * 8) * 2;
    const int bmx = lid >> 3, brr = lid & 7;
    const uint32_t bBase = smem_u32(sm_b)
        + (brr + (bmx & 1) * 8) * 272
        + (wn * 64 + (bmx >> 1) * 8) * 2;

    float acc[2][8][4];
#pragma unroll
    for (int i = 0; i < 2; i++)
#pragma unroll
        for (int j = 0; j < 8; j++)
#pragma unroll
            for (int k = 0; k < 4; k++) acc[i][j][k] = 0.0f;

    auto load_stage = [&](int st) {
        const __half* ga = arow + st * 32;
        const __half* gb = bgp + (size_t)st * 32 * N;
        const uint32_t da = sa0 + (st % 3) * BUFA;
        const uint32_t db = sb0 + (st % 3) * BUFB;
        CP16(da,      ga);
        CP16(da + 16, ga + 8);
        CP16(db,      gb);
        CP16(db + 16, gb + 8);
    };

    load_stage(0); CP_COMMIT();
    load_stage(1); CP_COMMIT();

    for (int s = 0; s < S; ++s) {
        cp_wait<1>();
        __syncthreads();
        if (s + 2 < S) load_stage(s + 2);
        CP_COMMIT();

        const uint32_t ab = (s % 3) * BUFA;
        const uint32_t bb = (s % 3) * BUFB;
#pragma unroll
        for (int kk = 0; kk < 32; kk += 16) {
            uint32_t af[2][4], bt[4][4];
#pragma unroll
            for (int mi = 0; mi < 2; mi++)
                LDM_X4(af[mi], aBase + ab + mi * 16 * 80 + kk * 2);
#pragma unroll
            for (int g = 0; g < 4; g++)
                LDM_X4_T(bt[g], bBase + bb + kk * 272 + g * 32);
#pragma unroll
            for (int mi = 0; mi < 2; mi++)
#pragma unroll
                for (int g = 0; g < 4; g++) {
                    mma16816(acc[mi][2 * g],     af[mi], bt[g][0], bt[g][1]);
                    mma16816(acc[mi][2 * g + 1], af[mi], bt[g][2], bt[g][3]);
                }
        }
    }

    // ---- epilogue ----
    const int lr = lid >> 2;
    const int lc = (lid & 3) * 2;
#pragma unroll
    for (int mi = 0; mi < 2; mi++) {
#pragma unroll
        for (int h = 0; h < 2; h++) {
            int rl = wm * 32 + mi * 16 + h * 8 + lr;
            int r  = bm * 128 + rl;
            int p = 0;
            float gw = 0.f;
            if (!sh) {
                p = plist_s[rl];
                if (p < 0) continue;
                gw = g_pw[p];
            }
            if (LAYER == 1) {
                __half* dh = sh ? (g_hs + (size_t)r * HID)
                                : (g_h  + (size_t)p * HID);
#pragma unroll
                for (int nj = 0; nj < 8; nj++) {
                    int cl = wn * 64 + nj * 8 + lc;
                    float v0 = acc[mi][nj][2 * h]     + bp[cl];
                    float v1 = acc[mi][nj][2 * h + 1] + bp[cl + 1];
                    v0 = (v0 > 0.f) ? v0 : 0.01f * v0;
                    v1 = (v1 > 0.f) ? v1 : 0.01f * v1;
                    *reinterpret_cast<__half2*>(dh + bn * 128 + cl) =
                        __floats2half2_rn(v0, v1);
                }
            } else if (sh) {
                float* d = g_sh + (size_t)r * DIM;
#pragma unroll
                for (int nj = 0; nj < 8; nj++) {
                    int cl = wn * 64 + nj * 8 + lc;
                    float2 v;
                    v.x = acc[mi][nj][2 * h]     + bp[cl];
                    v.y = acc[mi][nj][2 * h + 1] + bp[cl + 1];
                    *reinterpret_cast<float2*>(d + bn * 128 + cl) = v;
                }
            } else {
                float* d = g_moe2 + (size_t)p * DIM;
#pragma unroll
                for (int nj = 0; nj < 8; nj++) {
                    int cl = wn * 64 + nj * 8 + lc;
                    float2 v;
                    v.x = gw * (acc[mi][nj][2 * h]     + bp[cl]);
                    v.y = gw * (acc[mi][nj][2 * h + 1] + bp[cl + 1]);
                    *reinterpret_cast<float2*>(d + bn * 128 + cl) = v;
                }
            }
        }
    }
}

// ---------------- final mix (float4) -----------------------------------------
__global__ void combine_kernel(const float* __restrict__ alpha,
                               const float* __restrict__ beta,
                               float4* __restrict__ out) {
    float a = *alpha, b = *beta;
    float m  = fmaxf(a, b);
    float ea = expf(a - m), eb = expf(b - m);
    float inv = 1.0f / (ea + eb);
    float w0 = ea * inv, w1 = eb * inv;
    const int D4 = DIM / 4;
    const int n4 = T_TOK * D4;
    int i = blockIdx.x * blockDim.x + threadIdx.x;
    if (i >= n4) return;
    int t = i / D4, j = i - t * D4;
    const float4* m4 = reinterpret_cast<const float4*>(g_moe2);
    float4 m0 = m4[(size_t)(2 * t) * D4 + j];
    float4 m1 = m4[(size_t)(2 * t + 1) * D4 + j];
    float4 sv = reinterpret_cast<const float4*>(g_sh)[i];
    float4 o;
    o.x = w0 * sv.x + w1 * (m0.x + m1.x);
    o.y = w0 * sv.y + w1 * (m0.y + m1.y);
    o.z = w0 * sv.z + w1 * (m0.z + m1.z);
    o.w = w0 * sv.w + w1 * (m0.w + m1.w);
    out[i] = o;
}

// ---------------- launch ----------------------------------------------------
extern "C" void kernel_launch(void* const* d_in, const int* in_sizes, int n_in,
                              void* d_out, int out_size) {
    const float* x     = (const float*)d_in[0];
    const float* noise = (const float*)d_in[1];
    const float* Wr    = (const float*)d_in[2];
    const float* br    = (const float*)d_in[3];
    const float* W1    = (const float*)d_in[4];
    const float* b1    = (const float*)d_in[5];
    const float* W2    = (const float*)d_in[6];
    const float* b2    = (const float*)d_in[7];
    const float* Ws1   = (const float*)d_in[8];
    const float* bs1   = (const float*)d_in[9];
    const float* Ws2   = (const float*)d_in[10];
    const float* bs2   = (const float*)d_in[11];
    const float* alpha = (const float*)d_in[12];
    const float* beta  = (const float*)d_in[13];

    __half* w1h;  cudaGetSymbolAddress((void**)&w1h,  g_w1h);
    __half* w2h;  cudaGetSymbolAddress((void**)&w2h,  g_w2h);
    __half* ws1h; cudaGetSymbolAddress((void**)&ws1h, g_ws1h);
    __half* ws2h; cudaGetSymbolAddress((void**)&ws2h, g_ws2h);

    const int SMEM = 3 * 10240 + 3 * 8704;   // 56832
    cudaFuncSetAttribute(mma_gemm<1>, cudaFuncAttributeMaxDynamicSharedMemorySize, SMEM);
    cudaFuncSetAttribute(mma_gemm<2>, cudaFuncAttributeMaxDynamicSharedMemorySize, SMEM);

    cudaStream_t st1;
    cudaStreamCreateWithFlags(&st1, cudaStreamNonBlocking);
    cudaEvent_t evRoot, ev1;
    cudaEventCreateWithFlags(&evRoot, cudaEventDisableTiming);
    cudaEventCreateWithFlags(&ev1,    cudaEventDisableTiming);

    const int nW  = NEXP * DIM * HID / 4;
    const int nWs = DIM * HID / 4;
    const int nTot = 2 * (nW + nWs);

    // main-stream launches #1..#3 (after harness's poison memset = #0)
    zero_kernel<<<1, 32>>>();
    router_kernel<<<T_TOK / 4, 128>>>(x, noise, Wr, br);
    prep_x_kernel<<<(T_TOK * DIM / 4 + 255) / 256, 256>>>(x);

    cudaEventRecord(evRoot, 0);
    cudaStreamWaitEvent(st1, evRoot, 0);

    // launch #4: all weight conversion (overlaps router/prep on main)
    conv_all_kernel<<<(nTot + 255) / 256, 256, 0, st1>>>(
        (const float4*)W1, (const float4*)W2, (const float4*)Ws1, (const float4*)Ws2,
        (uint2*)w1h, (uint2*)w2h, (uint2*)ws1h, (uint2*)ws2h, nW, nWs);
    cudaEventRecord(ev1, st1);

    // launch #5: GEMM1  (target of ncu -s 5 -c 1)
    cudaStreamWaitEvent(0, ev1, 0);
    mma_gemm<1><<<dim3(HID / 128, T_TOK / 128, NEXP + 1), 256, SMEM>>>(b1, bs1);
    mma_gemm<2><<<dim3(DIM / 128, T_TOK / 128, NEXP + 1), 256, SMEM>>>(b2, bs2);
    combine_kernel<<<(T_TOK * DIM / 4 + 255) / 256, 256>>>(alpha, beta, (float4*)d_out);

    cudaEventDestroy(evRoot);
    cudaEventDestroy(ev1);
    cudaStreamDestroy(st1);
}

// round 11
// speedup vs baseline: 6.1072x; 1.0267x over previous
#include <cuda_runtime.h>
#include <cuda_fp16.h>
#include <cstdint>

#define T_TOK 2048
#define DIM   768
#define HID   3072
#define NEXP  8

// ---------------- scratch (device globals) ----------------------------------
__device__ int   g_cnt[NEXP];
__device__ int   g_plist[NEXP * T_TOK];
__device__ float g_pw[2 * T_TOK];
__device__ float g_moe2[(size_t)2 * T_TOK * DIM];   // per-pair L2 output
__device__ float g_sh[T_TOK * DIM];

__device__ __align__(16) __half g_x  [(size_t)T_TOK * DIM];
__device__ __align__(16) __half g_hs [(size_t)T_TOK * HID];
__device__ __align__(16) __half g_h  [(size_t)2 * T_TOK * HID];
__device__ __align__(16) __half g_w1h [(size_t)NEXP * DIM * HID];  // native [K,N]
__device__ __align__(16) __half g_ws1h[(size_t)DIM * HID];
__device__ __align__(16) __half g_w2h [(size_t)NEXP * HID * DIM];
__device__ __align__(16) __half g_ws2h[(size_t)HID * DIM];

// ---------------- helpers ----------------------------------------------------
__device__ __forceinline__ uint32_t smem_u32(const void* p) {
    uint32_t a;
    asm("{ .reg .u64 t; cvta.to.shared.u64 t, %1; cvt.u32.u64 %0, t; }"
        : "=r"(a) : "l"(p));
    return a;
}
#define CP16(saddr, gptr) \
    asm volatile("cp.async.cg.shared.global [%0], [%1], 16;" \
                 :: "r"(saddr), "l"(gptr) : "memory")
#define CP_COMMIT() asm volatile("cp.async.commit_group;" ::: "memory")
template <int N>
__device__ __forceinline__ void cp_wait() {
    asm volatile("cp.async.wait_group %0;" :: "n"(N) : "memory");
}
#define LDM_X4(r, addr) \
    asm volatile("ldmatrix.sync.aligned.m8n8.x4.shared.b16 {%0,%1,%2,%3}, [%4];" \
                 : "=r"((r)[0]), "=r"((r)[1]), "=r"((r)[2]), "=r"((r)[3]) \
                 : "r"(addr))
#define LDM_X4_T(r, addr) \
    asm volatile("ldmatrix.sync.aligned.m8n8.x4.trans.shared.b16 {%0,%1,%2,%3}, [%4];" \
                 : "=r"((r)[0]), "=r"((r)[1]), "=r"((r)[2]), "=r"((r)[3]) \
                 : "r"(addr))
__device__ __forceinline__ void mma16816(float* d, const uint32_t* a,
                                         uint32_t b0, uint32_t b1) {
    asm volatile(
        "mma.sync.aligned.m16n8k16.row.col.f32.f16.f16.f32 "
        "{%0,%1,%2,%3}, {%4,%5,%6,%7}, {%8,%9}, {%0,%1,%2,%3};"
        : "+f"(d[0]), "+f"(d[1]), "+f"(d[2]), "+f"(d[3])
        : "r"(a[0]), "r"(a[1]), "r"(a[2]), "r"(a[3]), "r"(b0), "r"(b1));
}

// ---------------- zero counters ----------------------------------------------
__global__ void zero_kernel() {
    if (threadIdx.x < NEXP) g_cnt[threadIdx.x] = 0;
}

// ---------------- router: one warp per token --------------------------------
__global__ void router_kernel(const float* __restrict__ x,
                              const float* __restrict__ noise,
                              const float* __restrict__ Wr,
                              const float* __restrict__ br) {
    int warp = (blockIdx.x * blockDim.x + threadIdx.x) >> 5;
    int lane = threadIdx.x & 31;
    if (warp >= T_TOK) return;
    const float* xr = x + warp * DIM;
    float acc[8] = {0.f, 0.f, 0.f, 0.f, 0.f, 0.f, 0.f, 0.f};
    for (int j = lane; j < DIM; j += 32) {
        float xv = xr[j];
        const float4* w4 = reinterpret_cast<const float4*>(Wr + j * NEXP);
        float4 wa = w4[0], wb = w4[1];
        acc[0] += xv * wa.x; acc[1] += xv * wa.y;
        acc[2] += xv * wa.z; acc[3] += xv * wa.w;
        acc[4] += xv * wb.x; acc[5] += xv * wb.y;
        acc[6] += xv * wb.z; acc[7] += xv * wb.w;
    }
#pragma unroll
    for (int off = 16; off; off >>= 1)
#pragma unroll
        for (int e = 0; e < 8; e++)
            acc[e] += __shfl_xor_sync(0xffffffffu, acc[e], off);
    if (lane == 0) {
        float lg[8];
#pragma unroll
        for (int e = 0; e < 8; e++)
            lg[e] = acc[e] + br[e] + 0.1f * noise[warp * NEXP + e];
        int i0 = 0;
#pragma unroll
        for (int e = 1; e < 8; e++) if (lg[e] > lg[i0]) i0 = e;
        int i1 = (i0 == 0) ? 1 : 0;
#pragma unroll
        for (int e = 0; e < 8; e++) if (e != i0 && lg[e] > lg[i1]) i1 = e;
        float e1 = expf(lg[i1] - lg[i0]);
        float w0 = 1.0f / (1.0f + e1);
        g_pw[2 * warp]     = w0;
        g_pw[2 * warp + 1] = e1 * w0;
        int p0 = atomicAdd(&g_cnt[i0], 1);
        g_plist[i0 * T_TOK + p0] = 2 * warp;
        int p1 = atomicAdd(&g_cnt[i1], 1);
        g_plist[i1 * T_TOK + p1] = 2 * warp + 1;
    }
}

// ---------------- prep: x -> fp16 -------------------------------------------
__global__ void prep_x_kernel(const float* __restrict__ x) {
    int i = blockIdx.x * blockDim.x + threadIdx.x;
    const int n4 = T_TOK * DIM / 4;
    if (i >= n4) return;
    float4 v = reinterpret_cast<const float4*>(x)[i];
    __half2 h0 = __floats2half2_rn(v.x, v.y);
    __half2 h1 = __floats2half2_rn(v.z, v.w);
    uint2 pk;
    pk.x = *reinterpret_cast<uint32_t*>(&h0);
    pk.y = *reinterpret_cast<uint32_t*>(&h1);
    reinterpret_cast<uint2*>(g_x)[i] = pk;
}

// ---------------- conv: one layer's weights (expert + shared) ----------------
__global__ void conv_w_kernel(const float4* __restrict__ srcE,
                              uint2* __restrict__ dstE, int nE,
                              const float4* __restrict__ srcS,
                              uint2* __restrict__ dstS, int nS) {
    int i = blockIdx.x * blockDim.x + threadIdx.x;
    const float4* src;
    uint2* dst;
    int j;
    if (i < nE)           { src = srcE; dst = dstE; j = i; }
    else if (i < nE + nS) { src = srcS; dst = dstS; j = i - nE; }
    else return;
    float4 v = src[j];
    __half2 h0 = __floats2half2_rn(v.x, v.y);
    __half2 h1 = __floats2half2_rn(v.z, v.w);
    uint2 pk;
    pk.x = *reinterpret_cast<uint32_t*>(&h0);
    pk.y = *reinterpret_cast<uint32_t*>(&h1);
    dst[j] = pk;
}

// ---------------- HMMA GEMM, 3-stage cp.async ring, occ=2 --------------------
// block 128x128, 8 warps 4(M)x2(N), warp tile 32x64, K-chunk 32.
// A smem: [row][k] 80B pitch; B smem: [k][n] 272B pitch (native [K,N] weights,
// ldmatrix.trans). One __syncthreads per K-chunk.
// grid.z: z<8 => expert z (gathered rows); z==8 => shared expert (dense).
template <int LAYER>
__global__ __launch_bounds__(256, 2)
void mma_gemm(const float* __restrict__ bias_moe,
              const float* __restrict__ bias_sh) {
    constexpr int K = (LAYER == 1) ? DIM : HID;
    constexpr int N = (LAYER == 1) ? HID : DIM;
    constexpr int S = K / 32;
    constexpr int BUFA = 128 * 80;    // 10240
    constexpr int BUFB = 32 * 272;    // 8704

    const int bn = blockIdx.x, bm = blockIdx.y, e = blockIdx.z;
    const bool sh = (e == NEXP);
    const int M = sh ? T_TOK : g_cnt[e];
    if (bm * 128 >= M) return;

    const __half* Bg;
    const float* bp;
    if (LAYER == 1) {
        Bg = sh ? g_ws1h : g_w1h + (size_t)e * DIM * HID;
        bp = (sh ? bias_sh : bias_moe + e * HID) + bn * 128;
    } else {
        Bg = sh ? g_ws2h : g_w2h + (size_t)e * HID * DIM;
        bp = (sh ? bias_sh : bias_moe + e * DIM) + bn * 128;
    }
    Bg += bn * 128;

    extern __shared__ __align__(16) char dsm[];
    char* sm_a = dsm;                 // 3 x BUFA
    char* sm_b = dsm + 3 * BUFA;      // 3 x BUFB
    __shared__ int plist_s[128];

    const int tid = threadIdx.x;
    const int lid = tid & 31, wid = tid >> 5;
    const int wm = wid >> 1, wn = wid & 1;

    if (!sh) {
        if (tid < 128) {
            int r = bm * 128 + tid;
            plist_s[tid] = (r < M) ? g_plist[e * T_TOK + tid + bm * 128] : -1;
        }
        __syncthreads();
    }

    // ---- A cp.async: 2 threads per row, 32B each ----
    const int lrow = tid >> 1;
    const int c4   = (tid & 1) * 2;
    const __half* arow;
    if (sh) {
        arow = ((LAYER == 1) ? g_x : g_hs) + (size_t)(bm * 128 + lrow) * K;
    } else {
        int p  = plist_s[lrow];
        int rr = (p >= 0) ? ((LAYER == 1) ? (p >> 1) : p) : 0;
        arow = ((LAYER == 1) ? g_x : g_h) + (size_t)rr * K;
    }
    arow += c4 * 8;
    const uint32_t sa0 = smem_u32(sm_a) + lrow * 80 + c4 * 16;

    // ---- B cp.async: [k][n] rows, 272B pitch ----
    const int brow_ = tid >> 3;
    const int bseg  = (tid & 7) * 2;
    const __half* bgp = Bg + (size_t)brow_ * N + bseg * 8;
    const uint32_t sb0 = smem_u32(sm_b) + brow_ * 272 + bseg * 16;

    // ---- ldmatrix bases ----
    const uint32_t aBase = smem_u32(sm_a)
        + (wm * 32 + ((lid >> 3) & 1) * 8 + (lid & 7)) * 80
        + (((lid >> 4) & 1) * 8) * 2;
    const int bmx = lid >> 3, brr = lid & 7;
    const uint32_t bBase = smem_u32(sm_b)
        + (brr + (bmx & 1) * 8) * 272
        + (wn * 64 + (bmx >> 1) * 8) * 2;

    float acc[2][8][4];
#pragma unroll
    for (int i = 0; i < 2; i++)
#pragma unroll
        for (int j = 0; j < 8; j++)
#pragma unroll
            for (int k = 0; k < 4; k++) acc[i][j][k] = 0.0f;

    auto load_stage = [&](int st) {
        const __half* ga = arow + st * 32;
        const __half* gb = bgp + (size_t)st * 32 * N;
        const uint32_t da = sa0 + (st % 3) * BUFA;
        const uint32_t db = sb0 + (st % 3) * BUFB;
        CP16(da,      ga);
        CP16(da + 16, ga + 8);
        CP16(db,      gb);
        CP16(db + 16, gb + 8);
    };

    load_stage(0); CP_COMMIT();
    load_stage(1); CP_COMMIT();

    for (int s = 0; s < S; ++s) {
        cp_wait<1>();
        __syncthreads();
        if (s + 2 < S) load_stage(s + 2);
        CP_COMMIT();

        const uint32_t ab = (s % 3) * BUFA;
        const uint32_t bb = (s % 3) * BUFB;
#pragma unroll
        for (int kk = 0; kk < 32; kk += 16) {
            uint32_t af[2][4], bt[4][4];
#pragma unroll
            for (int mi = 0; mi < 2; mi++)
                LDM_X4(af[mi], aBase + ab + mi * 16 * 80 + kk * 2);
#pragma unroll
            for (int g = 0; g < 4; g++)
                LDM_X4_T(bt[g], bBase + bb + kk * 272 + g * 32);
#pragma unroll
            for (int mi = 0; mi < 2; mi++)
#pragma unroll
                for (int g = 0; g < 4; g++) {
                    mma16816(acc[mi][2 * g],     af[mi], bt[g][0], bt[g][1]);
                    mma16816(acc[mi][2 * g + 1], af[mi], bt[g][2], bt[g][3]);
                }
        }
    }

    // ---- epilogue ----
    const int lr = lid >> 2;
    const int lc = (lid & 3) * 2;
#pragma unroll
    for (int mi = 0; mi < 2; mi++) {
#pragma unroll
        for (int h = 0; h < 2; h++) {
            int rl = wm * 32 + mi * 16 + h * 8 + lr;
            int r  = bm * 128 + rl;
            int p = 0;
            float gw = 0.f;
            if (!sh) {
                p = plist_s[rl];
                if (p < 0) continue;
                gw = g_pw[p];
            }
            if (LAYER == 1) {
                __half* dh = sh ? (g_hs + (size_t)r * HID)
                                : (g_h  + (size_t)p * HID);
#pragma unroll
                for (int nj = 0; nj < 8; nj++) {
                    int cl = wn * 64 + nj * 8 + lc;
                    float v0 = acc[mi][nj][2 * h]     + bp[cl];
                    float v1 = acc[mi][nj][2 * h + 1] + bp[cl + 1];
                    v0 = (v0 > 0.f) ? v0 : 0.01f * v0;
                    v1 = (v1 > 0.f) ? v1 : 0.01f * v1;
                    *reinterpret_cast<__half2*>(dh + bn * 128 + cl) =
                        __floats2half2_rn(v0, v1);
                }
            } else if (sh) {
                float* d = g_sh + (size_t)r * DIM;
#pragma unroll
                for (int nj = 0; nj < 8; nj++) {
                    int cl = wn * 64 + nj * 8 + lc;
                    float2 v;
                    v.x = acc[mi][nj][2 * h]     + bp[cl];
                    v.y = acc[mi][nj][2 * h + 1] + bp[cl + 1];
                    *reinterpret_cast<float2*>(d + bn * 128 + cl) = v;
                }
            } else {
                float* d = g_moe2 + (size_t)p * DIM;
#pragma unroll
                for (int nj = 0; nj < 8; nj++) {
                    int cl = wn * 64 + nj * 8 + lc;
                    float2 v;
                    v.x = gw * (acc[mi][nj][2 * h]     + bp[cl]);
                    v.y = gw * (acc[mi][nj][2 * h + 1] + bp[cl + 1]);
                    *reinterpret_cast<float2*>(d + bn * 128 + cl) = v;
                }
            }
        }
    }
}

// ---------------- final mix (float4) -----------------------------------------
__global__ void combine_kernel(const float* __restrict__ alpha,
                               const float* __restrict__ beta,
                               float4* __restrict__ out) {
    float a = *alpha, b = *beta;
    float m  = fmaxf(a, b);
    float ea = expf(a - m), eb = expf(b - m);
    float inv = 1.0f / (ea + eb);
    float w0 = ea * inv, w1 = eb * inv;
    const int D4 = DIM / 4;
    const int n4 = T_TOK * D4;
    int i = blockIdx.x * blockDim.x + threadIdx.x;
    if (i >= n4) return;
    int t = i / D4, j = i - t * D4;
    const float4* m4 = reinterpret_cast<const float4*>(g_moe2);
    float4 m0 = m4[(size_t)(2 * t) * D4 + j];
    float4 m1 = m4[(size_t)(2 * t + 1) * D4 + j];
    float4 sv = reinterpret_cast<const float4*>(g_sh)[i];
    float4 o;
    o.x = w0 * sv.x + w1 * (m0.x + m1.x);
    o.y = w0 * sv.y + w1 * (m0.y + m1.y);
    o.z = w0 * sv.z + w1 * (m0.z + m1.z);
    o.w = w0 * sv.w + w1 * (m0.w + m1.w);
    out[i] = o;
}

// ---------------- launch ----------------------------------------------------
extern "C" void kernel_launch(void* const* d_in, const int* in_sizes, int n_in,
                              void* d_out, int out_size) {
    const float* x     = (const float*)d_in[0];
    const float* noise = (const float*)d_in[1];
    const float* Wr    = (const float*)d_in[2];
    const float* br    = (const float*)d_in[3];
    const float* W1    = (const float*)d_in[4];
    const float* b1    = (const float*)d_in[5];
    const float* W2    = (const float*)d_in[6];
    const float* b2    = (const float*)d_in[7];
    const float* Ws1   = (const float*)d_in[8];
    const float* bs1   = (const float*)d_in[9];
    const float* Ws2   = (const float*)d_in[10];
    const float* bs2   = (const float*)d_in[11];
    const float* alpha = (const float*)d_in[12];
    const float* beta  = (const float*)d_in[13];

    __half* w1h;  cudaGetSymbolAddress((void**)&w1h,  g_w1h);
    __half* w2h;  cudaGetSymbolAddress((void**)&w2h,  g_w2h);
    __half* ws1h; cudaGetSymbolAddress((void**)&ws1h, g_ws1h);
    __half* ws2h; cudaGetSymbolAddress((void**)&ws2h, g_ws2h);

    const int SMEM = 3 * 10240 + 3 * 8704;   // 56832
    cudaFuncSetAttribute(mma_gemm<1>, cudaFuncAttributeMaxDynamicSharedMemorySize, SMEM);
    cudaFuncSetAttribute(mma_gemm<2>, cudaFuncAttributeMaxDynamicSharedMemorySize, SMEM);

    cudaStream_t stW, stX;
    cudaStreamCreateWithFlags(&stW, cudaStreamNonBlocking);
    cudaStreamCreateWithFlags(&stX, cudaStreamNonBlocking);
    cudaEvent_t evRoot, evW1, evW2, evX;
    cudaEventCreateWithFlags(&evRoot, cudaEventDisableTiming);
    cudaEventCreateWithFlags(&evW1,   cudaEventDisableTiming);
    cudaEventCreateWithFlags(&evW2,   cudaEventDisableTiming);
    cudaEventCreateWithFlags(&evX,    cudaEventDisableTiming);

    const int nW  = NEXP * DIM * HID / 4;
    const int nWs = DIM * HID / 4;
    const int nL  = nW + nWs;

    // fork side streams immediately
    cudaEventRecord(evRoot, 0);
    cudaStreamWaitEvent(stW, evRoot, 0);
    cudaStreamWaitEvent(stX, evRoot, 0);

    // side stream W: layer-1 weights, then layer-2 weights
    conv_w_kernel<<<(nL + 255) / 256, 256, 0, stW>>>(
        (const float4*)W1, (uint2*)w1h, nW, (const float4*)Ws1, (uint2*)ws1h, nWs);
    cudaEventRecord(evW1, stW);
    conv_w_kernel<<<(nL + 255) / 256, 256, 0, stW>>>(
        (const float4*)W2, (uint2*)w2h, nW, (const float4*)Ws2, (uint2*)ws2h, nWs);
    cudaEventRecord(evW2, stW);

    // side stream X: x -> fp16 (parallel with router)
    prep_x_kernel<<<(T_TOK * DIM / 4 + 255) / 256, 256, 0, stX>>>(x);
    cudaEventRecord(evX, stX);

    // main stream: routing
    zero_kernel<<<1, 32>>>();
    router_kernel<<<T_TOK / 4, 128>>>(x, noise, Wr, br);

    // GEMM1: needs router (program order) + prep_x + layer-1 weights
    cudaStreamWaitEvent(0, evX, 0);
    cudaStreamWaitEvent(0, evW1, 0);
    mma_gemm<1><<<dim3(HID / 128, T_TOK / 128, NEXP + 1), 256, SMEM>>>(b1, bs1);
    // GEMM2: additionally needs layer-2 weights (converted under GEMM1)
    cudaStreamWaitEvent(0, evW2, 0);
    mma_gemm<2><<<dim3(DIM / 128, T_TOK / 128, NEXP + 1), 256, SMEM>>>(b2, bs2);
    combine_kernel<<<(T_TOK * DIM / 4 + 255) / 256, 256>>>(alpha, beta, (float4*)d_out);

    cudaEventDestroy(evRoot);
    cudaEventDestroy(evW1);
    cudaEventDestroy(evW2);
    cudaEventDestroy(evX);
    cudaStreamDestroy(stW);
    cudaStreamDestroy(stX);
}